// round 6
// baseline (speedup 1.0000x reference)
#include <cuda_runtime.h>
#include <cuda_bf16.h>
#include <stdint.h>
#include <math.h>

#define NN 150000
#define EE 2400000
#define BBG 50000
#define HF 128
#define HF2 64

// weight pair offsets (uint32 bf162-pairs, layout [n][k/2] per weight, n-major)
#define WOFF1  0
#define WOFF2  8192
#define WOFF3  16384
#define WOFFC1 20480
#define WOFFC2 32768
#define WPAIRS 36864

#define COFF   4800000   // classifier intermediate offset in pair buffers

// ---------------- scratch (static device globals; no allocation) -------------
__device__ float    g_bufF[(size_t)NN * HF];
__device__ uint32_t g_aH[(size_t)NN * HF / 2];
__device__ uint32_t g_aL[(size_t)NN * HF / 2];
__device__ uint32_t g_wh[WPAIRS];
__device__ uint32_t g_wl[WPAIRS];
__device__ float g_dinv[NN];
__device__ float g_ew[EE];
__device__ int   g_deg[NN];
__device__ int   g_rowptr[NN + 1];
__device__ int   g_cursor[NN];
__device__ int   g_colsrc[EE];

// ---------------- helpers ----------------------------------------------------
__device__ __forceinline__ void split2(float x, float y, uint32_t& hi, uint32_t& lo) {
    __nv_bfloat16 hx = __float2bfloat16(x);
    __nv_bfloat16 hy = __float2bfloat16(y);
    float rx = x - __bfloat162float(hx);
    float ry = y - __bfloat162float(hy);
    __nv_bfloat162 h;
    h.x = hx; h.y = hy;
    __nv_bfloat162 l = __floats2bfloat162_rn(rx, ry);
    hi = reinterpret_cast<uint32_t&>(h);
    lo = reinterpret_cast<uint32_t&>(l);
}

__device__ __forceinline__ void mma16816(float c[4], const uint32_t a[4], const uint32_t b[2]) {
    asm volatile(
        "mma.sync.aligned.m16n8k16.row.col.f32.bf16.bf16.f32 "
        "{%0,%1,%2,%3}, {%4,%5,%6,%7}, {%8,%9}, {%0,%1,%2,%3};"
        : "+f"(c[0]), "+f"(c[1]), "+f"(c[2]), "+f"(c[3])
        : "r"(a[0]), "r"(a[1]), "r"(a[2]), "r"(a[3]), "r"(b[0]), "r"(b[1]));
}

__device__ __forceinline__ void ldsm4(uint32_t r[4], uint32_t saddr) {
    asm volatile(
        "ldmatrix.sync.aligned.m8n8.x4.shared.b16 {%0,%1,%2,%3}, [%4];"
        : "=r"(r[0]), "=r"(r[1]), "=r"(r[2]), "=r"(r[3]) : "r"(saddr));
}

// ---------------- setup kernels ---------------------------------------------
__global__ void k_zero_deg() {
    int i = blockIdx.x * blockDim.x + threadIdx.x;
    if (i < NN) g_deg[i] = 0;
}

__global__ void k_count(const int* __restrict__ ei) {
    int e = blockIdx.x * blockDim.x + threadIdx.x;
    if (e < EE) atomicAdd(&g_deg[ei[EE + e]], 1);
}

__global__ void k_scan() {
    __shared__ int s[1024];
    const int t = threadIdx.x;
    const int chunk = (NN + 1023) / 1024;
    const int start = t * chunk;
    const int end = min(start + chunk, NN);
    int sum = 0;
    for (int i = start; i < end; i++) sum += g_deg[i];
    s[t] = sum;
    __syncthreads();
    for (int off = 1; off < 1024; off <<= 1) {
        int v = (t >= off) ? s[t - off] : 0;
        __syncthreads();
        s[t] += v;
        __syncthreads();
    }
    if (t == 0) g_rowptr[NN] = s[1023];
    int base = (t == 0) ? 0 : s[t - 1];
    for (int i = start; i < end; i++) {
        g_rowptr[i] = base;
        g_cursor[i] = base;
        int d = g_deg[i];
        base += d;
        g_dinv[i] = rsqrtf((float)(d + 1));
    }
}

__global__ void k_scatter(const int* __restrict__ ei) {
    int e = blockIdx.x * blockDim.x + threadIdx.x;
    if (e < EE) {
        int srcn = ei[e];
        int dstn = ei[EE + e];
        int pos = atomicAdd(&g_cursor[dstn], 1);
        g_colsrc[pos] = srcn;
        g_ew[pos] = g_dinv[srcn] * g_dinv[dstn];
    }
}

// split weights once, n-major layout: wT[n][k/2] pairs
__global__ void k_split_w(const float* __restrict__ W1, const float* __restrict__ W2,
                          const float* __restrict__ W3, const float* __restrict__ Wc1,
                          const float* __restrict__ Wc2) {
    int p = blockIdx.x * blockDim.x + threadIdx.x;
    if (p >= WPAIRS) return;
    const float* src;
    int off, N, Kp;
    if (p < WOFF2)       { src = W1;  off = p - WOFF1;  N = 128; Kp = 64; }
    else if (p < WOFF3)  { src = W2;  off = p - WOFF2;  N = 128; Kp = 64; }
    else if (p < WOFFC1) { src = W3;  off = p - WOFF3;  N = 64;  Kp = 64; }
    else if (p < WOFFC2) { src = Wc1; off = p - WOFFC1; N = 128; Kp = 96; }
    else                 { src = Wc2; off = p - WOFFC2; N = 64;  Kp = 64; }
    int n = off / Kp, kp = off % Kp;
    float a = src[(size_t)(2 * kp) * N + n];
    float b = src[(size_t)(2 * kp + 1) * N + n];
    uint32_t h, l;
    split2(a, b, h, l);
    g_wh[p] = h;
    g_wl[p] = l;
}

__global__ void k_split_x(const float* __restrict__ x) {
    int i = blockIdx.x * blockDim.x + threadIdx.x;
    if (i >= NN * HF / 4) return;
    float4 v = ((const float4*)x)[i];
    uint32_t h0, l0, h1, l1;
    split2(v.x, v.y, h0, l0);
    split2(v.z, v.w, h1, l1);
    ((uint2*)g_aH)[i] = make_uint2(h0, h1);
    ((uint2*)g_aL)[i] = make_uint2(l0, l1);
}

// ---------------- bf16 split-MMA GEMM, ldmatrix fragments --------------------
// C[M,N] = A[M,K] @ W[K,N]. A: hi/lo bf162-pair arrays, row stride K/2.
// W: pre-split n-major [n][K/2] at wOff. Block 128x64, 8 warps (4x2).

#define BM 128
#define BN 64
#define SA 20    // A smem row stride (uint32) — 80B/row, 16B-aligned, conflict-free
#define SBS 20   // B smem n-row stride (uint32) — same properties

template <bool FUSE, bool OUTSPLIT>
__global__ void __launch_bounds__(256)
k_mma(const uint32_t* __restrict__ Ah, const uint32_t* __restrict__ Al,
      int wOff, const float* __restrict__ bias,
      float* __restrict__ Cf, uint32_t* __restrict__ OutH, uint32_t* __restrict__ OutL,
      int M, int K, int N) {
    __shared__ uint32_t sAh[BM * SA];
    __shared__ uint32_t sAl[BM * SA];
    __shared__ uint32_t sBh[BN * SBS];
    __shared__ uint32_t sBl[BN * SBS];

    const int tid = threadIdx.x;
    const int wid = tid >> 5;
    const int lane = tid & 31;
    const int wm = wid & 3;
    const int wn = wid >> 2;
    const int gid = lane >> 2;
    const int tig = lane & 3;
    const int bm = blockIdx.y * BM;
    const int bn = blockIdx.x * BN;
    const int Kp = K >> 1;

    const uint32_t sAhB = (uint32_t)__cvta_generic_to_shared(sAh);
    const uint32_t sAlB = (uint32_t)__cvta_generic_to_shared(sAl);
    const uint32_t sBhB = (uint32_t)__cvta_generic_to_shared(sBh);
    const uint32_t sBlB = (uint32_t)__cvta_generic_to_shared(sBl);

    float c[8][4];
#pragma unroll
    for (int i = 0; i < 8; i++)
#pragma unroll
        for (int j = 0; j < 4; j++) c[i][j] = 0.f;

    // ldmatrix lane addressing (word offsets within tile)
    const int aRow = lane & 15;              // A: m-row within 16
    const int aKh = (lane >> 4) * 4;         // A: k-half chunk
    const int bN = (lane >> 4) * 8 + (lane & 7);   // B: n within 16
    const int bKh = ((lane >> 3) & 1) * 4;   // B: k-half chunk

    for (int k0p = 0; k0p < Kp; k0p += 16) {
        // --- A tile stage: 128 rows x 16 pairs ---
#pragma unroll
        for (int i = 0; i < 2; i++) {
            int task = tid + i * 256;
            int row = task >> 2;
            int qg = (task & 3) * 4;
            int gr = bm + row;
            uint4 vh = make_uint4(0u, 0u, 0u, 0u);
            uint4 vl = make_uint4(0u, 0u, 0u, 0u);
            if (gr < M) {
                vh = *(const uint4*)&Ah[(size_t)gr * Kp + k0p + qg];
                vl = *(const uint4*)&Al[(size_t)gr * Kp + k0p + qg];
            }
            *(uint4*)&sAh[row * SA + qg] = vh;
            *(uint4*)&sAl[row * SA + qg] = vl;
        }
        // --- B tile stage: 64 n-rows x 16 pairs (n-major global) ---
        {
            int n = tid >> 2;
            int qg = (tid & 3) * 4;
            size_t gidx = (size_t)wOff + (size_t)(bn + n) * Kp + k0p + qg;
            *(uint4*)&sBh[n * SBS + qg] = *(const uint4*)&g_wh[gidx];
            *(uint4*)&sBl[n * SBS + qg] = *(const uint4*)&g_wl[gidx];
        }
        __syncthreads();

#pragma unroll
        for (int ks = 0; ks < 2; ks++) {
            uint32_t ah[2][4], al[2][4];
#pragma unroll
            for (int mt = 0; mt < 2; mt++) {
                uint32_t woff = (uint32_t)((wm * 32 + mt * 16 + aRow) * SA + ks * 8 + aKh) * 4u;
                ldsm4(ah[mt], sAhB + woff);
                ldsm4(al[mt], sAlB + woff);
            }
            uint32_t bh[4][2], bl[4][2];
#pragma unroll
            for (int j = 0; j < 2; j++) {
                uint32_t woff = (uint32_t)((wn * 32 + j * 16 + bN) * SBS + ks * 8 + bKh) * 4u;
                uint32_t rh[4], rl[4];
                ldsm4(rh, sBhB + woff);
                ldsm4(rl, sBlB + woff);
                bh[2 * j][0] = rh[0]; bh[2 * j][1] = rh[1];
                bh[2 * j + 1][0] = rh[2]; bh[2 * j + 1][1] = rh[3];
                bl[2 * j][0] = rl[0]; bl[2 * j][1] = rl[1];
                bl[2 * j + 1][0] = rl[2]; bl[2 * j + 1][1] = rl[3];
            }
#pragma unroll
            for (int mt = 0; mt < 2; mt++)
#pragma unroll
                for (int nt = 0; nt < 4; nt++) {
                    int t = mt * 4 + nt;
                    mma16816(c[t], ah[mt], bh[nt]);
                    mma16816(c[t], ah[mt], bl[nt]);
                    mma16816(c[t], al[mt], bh[nt]);
                }
        }
        __syncthreads();
    }

    // --- epilogue ---
#pragma unroll
    for (int mt = 0; mt < 2; mt++)
#pragma unroll
        for (int nt = 0; nt < 4; nt++) {
            int t = mt * 4 + nt;
            int gr0 = bm + wm * 32 + mt * 16 + gid;
            int gc = bn + wn * 32 + nt * 8 + tig * 2;
            float v0 = c[t][0], v1 = c[t][1], v2 = c[t][2], v3 = c[t][3];
            if (FUSE) {
                float b0 = bias[gc], b1 = bias[gc + 1];
                v0 = fmaxf(v0 + b0, 0.f);
                v1 = fmaxf(v1 + b1, 0.f);
                v2 = fmaxf(v2 + b0, 0.f);
                v3 = fmaxf(v3 + b1, 0.f);
            }
            if (OUTSPLIT) {
                uint32_t h, l;
                if (gr0 < M) {
                    split2(v0, v1, h, l);
                    size_t p = (size_t)gr0 * (N >> 1) + (gc >> 1);
                    OutH[p] = h;
                    OutL[p] = l;
                }
                if (gr0 + 8 < M) {
                    split2(v2, v3, h, l);
                    size_t p = (size_t)(gr0 + 8) * (N >> 1) + (gc >> 1);
                    OutH[p] = h;
                    OutL[p] = l;
                }
            } else {
                if (gr0 < M) *(float2*)&Cf[(size_t)gr0 * N + gc] = make_float2(v0, v1);
                if (gr0 + 8 < M) *(float2*)&Cf[(size_t)(gr0 + 8) * N + gc] = make_float2(v2, v3);
            }
        }
}

// ---------------- gather aggregation, split-bf16 output ----------------------
template <int F>
__global__ void k_agg(const float* __restrict__ h, const float* __restrict__ bias,
                      uint32_t* __restrict__ outH, uint32_t* __restrict__ outL) {
    int warp = (blockIdx.x * blockDim.x + threadIdx.x) >> 5;
    int lane = threadIdx.x & 31;
    if (warp >= NN) return;
    const int VPL = F / 32;
    float di = g_dinv[warp];
    float di2 = di * di;
    float acc[VPL];
    const float* hrow = h + (size_t)warp * F + lane * VPL;
    if (VPL == 4) {
        float4 v = *(const float4*)hrow;
        acc[0] = v.x * di2; acc[1] = v.y * di2; acc[2] = v.z * di2; acc[3] = v.w * di2;
    } else {
        float2 v = *(const float2*)hrow;
        acc[0] = v.x * di2; acc[1] = v.y * di2;
    }
    int beg = g_rowptr[warp];
    int end = g_rowptr[warp + 1];
    for (int j = beg; j < end; j++) {
        int s = g_colsrc[j];
        float w = g_ew[j];
        const float* hs = h + (size_t)s * F + lane * VPL;
        if (VPL == 4) {
            float4 v = *(const float4*)hs;
            acc[0] += v.x * w; acc[1] += v.y * w; acc[2] += v.z * w; acc[3] += v.w * w;
        } else {
            float2 v = *(const float2*)hs;
            acc[0] += v.x * w; acc[1] += v.y * w;
        }
    }
    if (VPL == 4) {
        float4 b = *(const float4*)&bias[lane * 4];
        float o0 = fmaxf(acc[0] + b.x, 0.f);
        float o1 = fmaxf(acc[1] + b.y, 0.f);
        float o2 = fmaxf(acc[2] + b.z, 0.f);
        float o3 = fmaxf(acc[3] + b.w, 0.f);
        uint32_t h0, l0, h1, l1;
        split2(o0, o1, h0, l0);
        split2(o2, o3, h1, l1);
        size_t p = (size_t)warp * (F / 2) + lane * 2;
        *(uint2*)&outH[p] = make_uint2(h0, h1);
        *(uint2*)&outL[p] = make_uint2(l0, l1);
    } else {
        float2 b = *(const float2*)&bias[lane * 2];
        float o0 = fmaxf(acc[0] + b.x, 0.f);
        float o1 = fmaxf(acc[1] + b.y, 0.f);
        uint32_t h0, l0;
        split2(o0, o1, h0, l0);
        size_t p = (size_t)warp * (F / 2) + lane;
        outH[p] = h0;
        outL[p] = l0;
    }
}

// ---------------- final 64->2 + log_softmax ----------------------------------
__global__ void k_final(const float* __restrict__ z, const float* __restrict__ Wc3,
                        const float* __restrict__ bc3, float* __restrict__ out) {
    __shared__ float sw[HF2 * 2];
    __shared__ float sb[2];
    if (threadIdx.x < HF2 * 2) sw[threadIdx.x] = Wc3[threadIdx.x];
    if (threadIdx.x < 2) sb[threadIdx.x] = bc3[threadIdx.x];
    __syncthreads();
    int g = blockIdx.x * blockDim.x + threadIdx.x;
    if (g >= BBG) return;
    const float* zr = z + (size_t)g * HF2;
    float a0 = sb[0], a1 = sb[1];
#pragma unroll
    for (int k = 0; k < HF2; k++) {
        float zv = zr[k];
        a0 += zv * sw[2 * k + 0];
        a1 += zv * sw[2 * k + 1];
    }
    float m = fmaxf(a0, a1);
    float l = logf(expf(a0 - m) + expf(a1 - m));
    out[2 * g + 0] = a0 - m - l;
    out[2 * g + 1] = a1 - m - l;
}

// ---------------- launch -----------------------------------------------------
extern "C" void kernel_launch(void* const* d_in, const int* in_sizes, int n_in,
                              void* d_out, int out_size) {
    const float* x   = (const float*)d_in[0];
    const int*   ei  = (const int*)d_in[1];
    const float* W1  = (const float*)d_in[2];
    const float* b1  = (const float*)d_in[3];
    const float* W2  = (const float*)d_in[4];
    const float* b2  = (const float*)d_in[5];
    const float* W3  = (const float*)d_in[6];
    const float* b3  = (const float*)d_in[7];
    const float* Wc1 = (const float*)d_in[8];
    const float* bc1 = (const float*)d_in[9];
    const float* Wc2 = (const float*)d_in[10];
    const float* bc2 = (const float*)d_in[11];
    const float* Wc3 = (const float*)d_in[12];
    const float* bc3 = (const float*)d_in[13];
    float* out = (float*)d_out;

    float* bufF;
    uint32_t* aH;
    uint32_t* aL;
    cudaGetSymbolAddress((void**)&bufF, g_bufF);
    cudaGetSymbolAddress((void**)&aH, g_aH);
    cudaGetSymbolAddress((void**)&aL, g_aL);

    // --- preprocessing ---
    k_zero_deg<<<(NN + 255) / 256, 256>>>();
    k_count<<<(EE + 255) / 256, 256>>>(ei);
    k_scan<<<1, 1024>>>();
    k_scatter<<<(EE + 255) / 256, 256>>>(ei);
    k_split_w<<<(WPAIRS + 255) / 256, 256>>>(W1, W2, W3, Wc1, Wc2);
    k_split_x<<<(NN * HF / 4 + 255) / 256, 256>>>(x);

    const int aggBlocks = (NN * 32 + 255) / 256;
    const int mRows = (NN + BM - 1) / BM;
    const int cRows = (BBG + BM - 1) / BM;
    dim3 g1(HF / BN, mRows);
    dim3 g3(HF2 / BN, mRows);
    dim3 gc1(HF / BN, cRows);
    dim3 gc2(HF2 / BN, cRows);

    // layer 1
    k_mma<false, false><<<g1, 256>>>(aH, aL, WOFF1, nullptr, bufF, nullptr, nullptr, NN, HF, HF);
    k_agg<HF><<<aggBlocks, 256>>>(bufF, b1, aH, aL);
    // layer 2
    k_mma<false, false><<<g1, 256>>>(aH, aL, WOFF2, nullptr, bufF, nullptr, nullptr, NN, HF, HF);
    k_agg<HF><<<aggBlocks, 256>>>(bufF, b2, aH, aL);
    // layer 3 (128 -> 64)
    k_mma<false, false><<<g3, 256>>>(aH, aL, WOFF3, nullptr, bufF, nullptr, nullptr, NN, HF, HF2);
    k_agg<HF2><<<aggBlocks, 256>>>(bufF, b3, aH, aL);
    // classifier: input viewed as [50000, 192] (96 pairs/row)
    k_mma<true, true><<<gc1, 256>>>(aH, aL, WOFFC1, bc1, nullptr, aH + COFF, aL + COFF,
                                    BBG, 3 * HF2, HF);
    k_mma<true, false><<<gc2, 256>>>(aH + COFF, aL + COFF, WOFFC2, bc2, bufF, nullptr, nullptr,
                                     BBG, HF, HF2);
    // final 64->2 + log_softmax
    k_final<<<(BBG + 255) / 256, 256>>>(bufF, Wc3, bc3, out);
}

// round 7
// speedup vs baseline: 1.6842x; 1.6842x over previous
#include <cuda_runtime.h>
#include <cuda_bf16.h>
#include <stdint.h>
#include <math.h>

#define NN 150000
#define EE 2400000
#define BBG 50000
#define HF 128
#define HF2 64

// weight pair offsets (uint32 bf162-pairs, layout [n][k/2] per weight, n-major)
#define WOFF1  0
#define WOFF2  8192
#define WOFF3  16384
#define WOFFC1 20480
#define WOFFC2 32768
#define WPAIRS 36864

#define COFF   4800000   // classifier intermediate offset in pair buffers
#define SCB    147       // scan blocks: ceil(150000/1024)

// ---------------- scratch (static device globals; no allocation) -------------
__device__ float    g_bufF[(size_t)NN * HF];
__device__ uint32_t g_aH[(size_t)NN * HF / 2];
__device__ uint32_t g_aL[(size_t)NN * HF / 2];
__device__ uint32_t g_wh[WPAIRS];
__device__ uint32_t g_wl[WPAIRS];
__device__ float g_dinv[NN];
__device__ float g_ew[EE];
__device__ int   g_deg[NN];
__device__ int   g_rowptr[NN + 1];
__device__ int   g_cursor[NN];
__device__ int   g_colsrc[EE];
__device__ int   g_part[256];

// ---------------- helpers ----------------------------------------------------
__device__ __forceinline__ void split2(float x, float y, uint32_t& hi, uint32_t& lo) {
    __nv_bfloat16 hx = __float2bfloat16(x);
    __nv_bfloat16 hy = __float2bfloat16(y);
    float rx = x - __bfloat162float(hx);
    float ry = y - __bfloat162float(hy);
    __nv_bfloat162 h;
    h.x = hx; h.y = hy;
    __nv_bfloat162 l = __floats2bfloat162_rn(rx, ry);
    hi = reinterpret_cast<uint32_t&>(h);
    lo = reinterpret_cast<uint32_t&>(l);
}

__device__ __forceinline__ void mma16816(float c[4], const uint32_t a[4], const uint32_t b[2]) {
    asm volatile(
        "mma.sync.aligned.m16n8k16.row.col.f32.bf16.bf16.f32 "
        "{%0,%1,%2,%3}, {%4,%5,%6,%7}, {%8,%9}, {%0,%1,%2,%3};"
        : "+f"(c[0]), "+f"(c[1]), "+f"(c[2]), "+f"(c[3])
        : "r"(a[0]), "r"(a[1]), "r"(a[2]), "r"(a[3]), "r"(b[0]), "r"(b[1]));
}

__device__ __forceinline__ void ldsm4(uint32_t r[4], uint32_t saddr) {
    asm volatile(
        "ldmatrix.sync.aligned.m8n8.x4.shared.b16 {%0,%1,%2,%3}, [%4];"
        : "=r"(r[0]), "=r"(r[1]), "=r"(r[2]), "=r"(r[3]) : "r"(saddr));
}

__device__ __forceinline__ void cpasync16(uint32_t smem, const void* gptr) {
    asm volatile("cp.async.cg.shared.global [%0], [%1], 16;" :: "r"(smem), "l"(gptr));
}
__device__ __forceinline__ void cp_commit() {
    asm volatile("cp.async.commit_group;");
}
template <int Nw>
__device__ __forceinline__ void cp_wait() {
    asm volatile("cp.async.wait_group %0;" :: "n"(Nw));
}

// ---------------- setup kernels ---------------------------------------------
__global__ void k_zero_deg() {
    int i = blockIdx.x * blockDim.x + threadIdx.x;
    if (i < NN) g_deg[i] = 0;
}

__global__ void k_count(const int* __restrict__ ei) {
    int e = blockIdx.x * blockDim.x + threadIdx.x;
    if (e < EE) atomicAdd(&g_deg[ei[EE + e]], 1);
}

// block sums of degrees
__global__ void k_scan1() {
    __shared__ int s[1024];
    int t = threadIdx.x;
    int i = blockIdx.x * 1024 + t;
    s[t] = (i < NN) ? g_deg[i] : 0;
    __syncthreads();
    for (int off = 512; off; off >>= 1) {
        if (t < off) s[t] += s[t + off];
        __syncthreads();
    }
    if (t == 0) g_part[blockIdx.x] = s[0];
}

// exclusive scan of block sums (1 block, 256 threads, SCB<=256)
__global__ void k_scan2() {
    __shared__ int s[256];
    int t = threadIdx.x;
    int v = (t < SCB) ? g_part[t] : 0;
    s[t] = v;
    __syncthreads();
    for (int off = 1; off < 256; off <<= 1) {
        int u = (t >= off) ? s[t - off] : 0;
        __syncthreads();
        s[t] += u;
        __syncthreads();
    }
    if (t < SCB) g_part[t] = s[t] - v;
    if (t == 255) g_rowptr[NN] = s[255];
}

// per-block exclusive scan + base; write rowptr/cursor/dinv
__global__ void k_scan3() {
    __shared__ int s[1024];
    int t = threadIdx.x;
    int i = blockIdx.x * 1024 + t;
    int d = (i < NN) ? g_deg[i] : 0;
    s[t] = d;
    __syncthreads();
    for (int off = 1; off < 1024; off <<= 1) {
        int u = (t >= off) ? s[t - off] : 0;
        __syncthreads();
        s[t] += u;
        __syncthreads();
    }
    if (i < NN) {
        int excl = s[t] - d + g_part[blockIdx.x];
        g_rowptr[i] = excl;
        g_cursor[i] = excl;
        g_dinv[i] = rsqrtf((float)(d + 1));
    }
}

__global__ void k_scatter(const int* __restrict__ ei) {
    int e = blockIdx.x * blockDim.x + threadIdx.x;
    if (e < EE) {
        int srcn = ei[e];
        int dstn = ei[EE + e];
        int pos = atomicAdd(&g_cursor[dstn], 1);
        g_colsrc[pos] = srcn;
        g_ew[pos] = g_dinv[srcn] * g_dinv[dstn];
    }
}

// split weights once, n-major layout: wT[n][k/2] pairs
__global__ void k_split_w(const float* __restrict__ W1, const float* __restrict__ W2,
                          const float* __restrict__ W3, const float* __restrict__ Wc1,
                          const float* __restrict__ Wc2) {
    int p = blockIdx.x * blockDim.x + threadIdx.x;
    if (p >= WPAIRS) return;
    const float* src;
    int off, N, Kp;
    if (p < WOFF2)       { src = W1;  off = p - WOFF1;  N = 128; Kp = 64; }
    else if (p < WOFF3)  { src = W2;  off = p - WOFF2;  N = 128; Kp = 64; }
    else if (p < WOFFC1) { src = W3;  off = p - WOFF3;  N = 64;  Kp = 64; }
    else if (p < WOFFC2) { src = Wc1; off = p - WOFFC1; N = 128; Kp = 96; }
    else                 { src = Wc2; off = p - WOFFC2; N = 64;  Kp = 64; }
    int n = off / Kp, kp = off % Kp;
    float a = src[(size_t)(2 * kp) * N + n];
    float b = src[(size_t)(2 * kp + 1) * N + n];
    uint32_t h, l;
    split2(a, b, h, l);
    g_wh[p] = h;
    g_wl[p] = l;
}

__global__ void k_split_x(const float* __restrict__ x) {
    int i = blockIdx.x * blockDim.x + threadIdx.x;
    if (i >= NN * HF / 4) return;
    float4 v = ((const float4*)x)[i];
    uint32_t h0, l0, h1, l1;
    split2(v.x, v.y, h0, l0);
    split2(v.z, v.w, h1, l1);
    ((uint2*)g_aH)[i] = make_uint2(h0, h1);
    ((uint2*)g_aL)[i] = make_uint2(l0, l1);
}

// ---------------- bf16 split-MMA GEMM, cp.async double-buffered --------------
// C[M,N] = A[M,K] @ W[K,N]. A: hi/lo bf162-pair arrays, row stride K/2.
// W: pre-split n-major [n][K/2] at wOff. Block tile BM x BNT, BNT == N.
// 8 warps: 4 m-warps (32 rows) x 2 n-warps (BNT/2 cols).

#define BM 128
#define SA 20    // A smem row stride (uint32): 80B, 16B aligned, ldmatrix conflict-free
#define SBS 20   // B smem n-row stride

template <int BNT, bool FUSE, bool OUTSPLIT>
__global__ void __launch_bounds__(256)
k_mma(const uint32_t* __restrict__ Ah, const uint32_t* __restrict__ Al,
      int wOff, const float* __restrict__ bias,
      float* __restrict__ Cf, uint32_t* __restrict__ OutH, uint32_t* __restrict__ OutL,
      int M, int K) {
    constexpr int NT = BNT / 16;           // n8-fragments per warp (8 or 4)
    constexpr int AW = BM * SA;            // words per A matrix stage
    constexpr int BW = BNT * SBS;          // words per B matrix stage
    constexpr int SW = 2 * AW + 2 * BW;    // words per stage

    extern __shared__ uint32_t smem[];

    const int tid = threadIdx.x;
    const int wid = tid >> 5;
    const int lane = tid & 31;
    const int wm = wid & 3;
    const int wn = wid >> 2;
    const int gid = lane >> 2;
    const int tig = lane & 3;
    const int bm = blockIdx.y * BM;
    const int Kp = K >> 1;
    const int KT = Kp >> 4;

    const uint32_t smB = (uint32_t)__cvta_generic_to_shared(smem);

    float c[2][NT][4];
#pragma unroll
    for (int mt = 0; mt < 2; mt++)
#pragma unroll
        for (int nt = 0; nt < NT; nt++)
#pragma unroll
            for (int j = 0; j < 4; j++) c[mt][nt][j] = 0.f;

    // ldmatrix lane addressing
    const int aRow = lane & 15;
    const int aKh = (lane >> 4) * 4;
    const int bN = (lane >> 4) * 8 + (lane & 7);
    const int bKh = ((lane >> 3) & 1) * 4;

    // stage prefetch: A (128x4 chunks)x2 + B (BNTx4 chunks)x2
    auto prefetch = [&](int kt, int buf) {
        const int k0p = kt * 16;
        uint32_t base = smB + (uint32_t)buf * SW * 4u;
#pragma unroll
        for (int i = 0; i < 2; i++) {
            int task = tid + i * 256;      // 0..511
            int row = task >> 2;
            int qg = (task & 3) * 4;
            int gr = bm + row;
            if (gr >= M) gr = M - 1;       // clamp; masked at epilogue
            size_t gofs = (size_t)gr * Kp + k0p + qg;
            uint32_t so = (uint32_t)(row * SA + qg) * 4u;
            cpasync16(base + so, &Ah[gofs]);
            cpasync16(base + AW * 4u + so, &Al[gofs]);
        }
#pragma unroll
        for (int i = 0; i < BNT / 64; i++) {
            int task = tid + i * 256;      // BNT*4 tasks
            int n = task >> 2;
            int qg = (task & 3) * 4;
            size_t gofs = (size_t)wOff + (size_t)n * Kp + k0p + qg;
            uint32_t so = (uint32_t)(n * SBS + qg) * 4u;
            cpasync16(base + 2u * AW * 4u + so, &g_wh[gofs]);
            cpasync16(base + (2u * AW + BW) * 4u + so, &g_wl[gofs]);
        }
        cp_commit();
    };

    prefetch(0, 0);

    for (int kt = 0; kt < KT; kt++) {
        const int buf = kt & 1;
        if (kt + 1 < KT) {
            prefetch(kt + 1, buf ^ 1);
            cp_wait<1>();
        } else {
            cp_wait<0>();
        }
        __syncthreads();

        uint32_t sAhB = smB + (uint32_t)buf * SW * 4u;
        uint32_t sAlB = sAhB + AW * 4u;
        uint32_t sBhB = sAlB + AW * 4u;
        uint32_t sBlB = sBhB + BW * 4u;

#pragma unroll
        for (int ks = 0; ks < 2; ks++) {
            uint32_t ah[2][4], al[2][4];
#pragma unroll
            for (int mt = 0; mt < 2; mt++) {
                uint32_t woff = (uint32_t)((wm * 32 + mt * 16 + aRow) * SA + ks * 8 + aKh) * 4u;
                ldsm4(ah[mt], sAhB + woff);
                ldsm4(al[mt], sAlB + woff);
            }
            uint32_t bh[NT][2], bl[NT][2];
#pragma unroll
            for (int j = 0; j < NT / 2; j++) {
                uint32_t woff = (uint32_t)((wn * (BNT / 2) + j * 16 + bN) * SBS + ks * 8 + bKh) * 4u;
                uint32_t rh[4], rl[4];
                ldsm4(rh, sBhB + woff);
                ldsm4(rl, sBlB + woff);
                bh[2 * j][0] = rh[0]; bh[2 * j][1] = rh[1];
                bh[2 * j + 1][0] = rh[2]; bh[2 * j + 1][1] = rh[3];
                bl[2 * j][0] = rl[0]; bl[2 * j][1] = rl[1];
                bl[2 * j + 1][0] = rl[2]; bl[2 * j + 1][1] = rl[3];
            }
#pragma unroll
            for (int mt = 0; mt < 2; mt++)
#pragma unroll
                for (int nt = 0; nt < NT; nt++) {
                    mma16816(c[mt][nt], ah[mt], bh[nt]);
                    mma16816(c[mt][nt], ah[mt], bl[nt]);
                    mma16816(c[mt][nt], al[mt], bh[nt]);
                }
        }
        __syncthreads();
    }

    // --- epilogue ---
    const int N = BNT;
#pragma unroll
    for (int mt = 0; mt < 2; mt++)
#pragma unroll
        for (int nt = 0; nt < NT; nt++) {
            int gr0 = bm + wm * 32 + mt * 16 + gid;
            int gc = wn * (BNT / 2) + nt * 8 + tig * 2;
            float v0 = c[mt][nt][0], v1 = c[mt][nt][1];
            float v2 = c[mt][nt][2], v3 = c[mt][nt][3];
            if (FUSE) {
                float b0 = bias[gc], b1 = bias[gc + 1];
                v0 = fmaxf(v0 + b0, 0.f);
                v1 = fmaxf(v1 + b1, 0.f);
                v2 = fmaxf(v2 + b0, 0.f);
                v3 = fmaxf(v3 + b1, 0.f);
            }
            if (OUTSPLIT) {
                uint32_t h, l;
                if (gr0 < M) {
                    split2(v0, v1, h, l);
                    size_t p = (size_t)gr0 * (N >> 1) + (gc >> 1);
                    OutH[p] = h;
                    OutL[p] = l;
                }
                if (gr0 + 8 < M) {
                    split2(v2, v3, h, l);
                    size_t p = (size_t)(gr0 + 8) * (N >> 1) + (gc >> 1);
                    OutH[p] = h;
                    OutL[p] = l;
                }
            } else {
                if (gr0 < M) *(float2*)&Cf[(size_t)gr0 * N + gc] = make_float2(v0, v1);
                if (gr0 + 8 < M) *(float2*)&Cf[(size_t)(gr0 + 8) * N + gc] = make_float2(v2, v3);
            }
        }
}

// ---------------- gather aggregation, split-bf16 output ----------------------
template <int F>
__global__ void k_agg(const float* __restrict__ h, const float* __restrict__ bias,
                      uint32_t* __restrict__ outH, uint32_t* __restrict__ outL) {
    int warp = (blockIdx.x * blockDim.x + threadIdx.x) >> 5;
    int lane = threadIdx.x & 31;
    if (warp >= NN) return;
    const int VPL = F / 32;
    float di = g_dinv[warp];
    float di2 = di * di;
    float acc[VPL];
    const float* hrow = h + (size_t)warp * F + lane * VPL;
    if (VPL == 4) {
        float4 v = *(const float4*)hrow;
        acc[0] = v.x * di2; acc[1] = v.y * di2; acc[2] = v.z * di2; acc[3] = v.w * di2;
    } else {
        float2 v = *(const float2*)hrow;
        acc[0] = v.x * di2; acc[1] = v.y * di2;
    }
    int beg = g_rowptr[warp];
    int end = g_rowptr[warp + 1];
    for (int j = beg; j < end; j++) {
        int s = g_colsrc[j];
        float w = g_ew[j];
        const float* hs = h + (size_t)s * F + lane * VPL;
        if (VPL == 4) {
            float4 v = *(const float4*)hs;
            acc[0] += v.x * w; acc[1] += v.y * w; acc[2] += v.z * w; acc[3] += v.w * w;
        } else {
            float2 v = *(const float2*)hs;
            acc[0] += v.x * w; acc[1] += v.y * w;
        }
    }
    if (VPL == 4) {
        float4 b = *(const float4*)&bias[lane * 4];
        float o0 = fmaxf(acc[0] + b.x, 0.f);
        float o1 = fmaxf(acc[1] + b.y, 0.f);
        float o2 = fmaxf(acc[2] + b.z, 0.f);
        float o3 = fmaxf(acc[3] + b.w, 0.f);
        uint32_t h0, l0, h1, l1;
        split2(o0, o1, h0, l0);
        split2(o2, o3, h1, l1);
        size_t p = (size_t)warp * (F / 2) + lane * 2;
        *(uint2*)&outH[p] = make_uint2(h0, h1);
        *(uint2*)&outL[p] = make_uint2(l0, l1);
    } else {
        float2 b = *(const float2*)&bias[lane * 2];
        float o0 = fmaxf(acc[0] + b.x, 0.f);
        float o1 = fmaxf(acc[1] + b.y, 0.f);
        uint32_t h0, l0;
        split2(o0, o1, h0, l0);
        size_t p = (size_t)warp * (F / 2) + lane;
        outH[p] = h0;
        outL[p] = l0;
    }
}

// ---------------- final 64->2 + log_softmax ----------------------------------
__global__ void k_final(const float* __restrict__ z, const float* __restrict__ Wc3,
                        const float* __restrict__ bc3, float* __restrict__ out) {
    __shared__ float sw[HF2 * 2];
    __shared__ float sb[2];
    if (threadIdx.x < HF2 * 2) sw[threadIdx.x] = Wc3[threadIdx.x];
    if (threadIdx.x < 2) sb[threadIdx.x] = bc3[threadIdx.x];
    __syncthreads();
    int g = blockIdx.x * blockDim.x + threadIdx.x;
    if (g >= BBG) return;
    const float* zr = z + (size_t)g * HF2;
    float a0 = sb[0], a1 = sb[1];
#pragma unroll
    for (int k = 0; k < HF2; k++) {
        float zv = zr[k];
        a0 += zv * sw[2 * k + 0];
        a1 += zv * sw[2 * k + 1];
    }
    float m = fmaxf(a0, a1);
    float l = logf(expf(a0 - m) + expf(a1 - m));
    out[2 * g + 0] = a0 - m - l;
    out[2 * g + 1] = a1 - m - l;
}

// ---------------- launch -----------------------------------------------------
extern "C" void kernel_launch(void* const* d_in, const int* in_sizes, int n_in,
                              void* d_out, int out_size) {
    const float* x   = (const float*)d_in[0];
    const int*   ei  = (const int*)d_in[1];
    const float* W1  = (const float*)d_in[2];
    const float* b1  = (const float*)d_in[3];
    const float* W2  = (const float*)d_in[4];
    const float* b2  = (const float*)d_in[5];
    const float* W3  = (const float*)d_in[6];
    const float* b3  = (const float*)d_in[7];
    const float* Wc1 = (const float*)d_in[8];
    const float* bc1 = (const float*)d_in[9];
    const float* Wc2 = (const float*)d_in[10];
    const float* bc2 = (const float*)d_in[11];
    const float* Wc3 = (const float*)d_in[12];
    const float* bc3 = (const float*)d_in[13];
    float* out = (float*)d_out;

    float* bufF;
    uint32_t* aH;
    uint32_t* aL;
    cudaGetSymbolAddress((void**)&bufF, g_bufF);
    cudaGetSymbolAddress((void**)&aH, g_aH);
    cudaGetSymbolAddress((void**)&aL, g_aL);

    // dynamic smem sizes (bytes): 2 stages
    const int SM128 = 2 * (2 * BM * SA + 2 * 128 * SBS) * 4;   // 81920
    const int SM64  = 2 * (2 * BM * SA + 2 * 64 * SBS) * 4;    // 61440
    static bool attrDone = false;
    if (!attrDone) {
        cudaFuncSetAttribute(k_mma<128, false, false>, cudaFuncAttributeMaxDynamicSharedMemorySize, SM128);
        cudaFuncSetAttribute(k_mma<128, true, true>,   cudaFuncAttributeMaxDynamicSharedMemorySize, SM128);
        cudaFuncSetAttribute(k_mma<64, false, false>,  cudaFuncAttributeMaxDynamicSharedMemorySize, SM64);
        cudaFuncSetAttribute(k_mma<64, true, false>,   cudaFuncAttributeMaxDynamicSharedMemorySize, SM64);
        attrDone = true;
    }

    // --- preprocessing ---
    k_zero_deg<<<(NN + 255) / 256, 256>>>();
    k_count<<<(EE + 255) / 256, 256>>>(ei);
    k_scan1<<<SCB, 1024>>>();
    k_scan2<<<1, 256>>>();
    k_scan3<<<SCB, 1024>>>();
    k_scatter<<<(EE + 255) / 256, 256>>>(ei);
    k_split_w<<<(WPAIRS + 255) / 256, 256>>>(W1, W2, W3, Wc1, Wc2);
    k_split_x<<<(NN * HF / 4 + 255) / 256, 256>>>(x);

    const int aggBlocks = (NN * 32 + 255) / 256;
    dim3 gN(1, (NN + BM - 1) / BM);     // 1172 row-blocks
    dim3 gC(1, (BBG + BM - 1) / BM);    // 391 row-blocks

    // layer 1
    k_mma<128, false, false><<<gN, 256, SM128>>>(aH, aL, WOFF1, nullptr, bufF, nullptr, nullptr, NN, HF);
    k_agg<HF><<<aggBlocks, 256>>>(bufF, b1, aH, aL);
    // layer 2
    k_mma<128, false, false><<<gN, 256, SM128>>>(aH, aL, WOFF2, nullptr, bufF, nullptr, nullptr, NN, HF);
    k_agg<HF><<<aggBlocks, 256>>>(bufF, b2, aH, aL);
    // layer 3 (128 -> 64)
    k_mma<64, false, false><<<gN, 256, SM64>>>(aH, aL, WOFF3, nullptr, bufF, nullptr, nullptr, NN, HF);
    k_agg<HF2><<<aggBlocks, 256>>>(bufF, b3, aH, aL);
    // classifier: input viewed as [50000, 192] (96 pairs/row)
    k_mma<128, true, true><<<gC, 256, SM128>>>(aH, aL, WOFFC1, bc1, nullptr, aH + COFF, aL + COFF, BBG, 3 * HF2);
    k_mma<64, true, false><<<gC, 256, SM64>>>(aH + COFF, aL + COFF, WOFFC2, bc2, bufF, nullptr, nullptr, BBG, HF);
    // final 64->2 + log_softmax
    k_final<<<(BBG + 255) / 256, 256>>>(bufF, Wc3, bc3, out);
}

// round 8
// speedup vs baseline: 1.8564x; 1.1022x over previous
#include <cuda_runtime.h>
#include <cuda_bf16.h>
#include <cuda_fp16.h>
#include <stdint.h>
#include <math.h>

#define NN 150000
#define EE 2400000
#define BBG 50000
#define HF 128
#define HF2 64

#define WOFF1  0
#define WOFF2  8192
#define WOFF3  16384
#define WOFFC1 20480
#define WOFFC2 32768
#define WPAIRS 36864

#define COFF   4800000   // classifier intermediate offset in pair buffers
#define SCB    147       // scan blocks: ceil(150000/1024)

// ---------------- scratch (static device globals; no allocation) -------------
__device__ float    g_bufF[(size_t)BBG * HF2];        // fp32 (classifier c2 out)
__device__ uint32_t g_bufH[(size_t)NN * HF / 2];      // half2 GEMM outputs (agg input)
__device__ uint32_t g_aH[(size_t)NN * HF / 2];        // split activations hi (bf162 pairs)
__device__ uint32_t g_aL[(size_t)NN * HF / 2];        // split activations lo
__device__ uint32_t g_wh[WPAIRS];
__device__ uint32_t g_wl[WPAIRS];
__device__ float g_dinv[NN];
__device__ int2  g_edge[EE];                          // {src, weight-as-int}
__device__ int   g_deg[NN];
__device__ int   g_rowptr[NN + 1];
__device__ int   g_cursor[NN];
__device__ int   g_part[256];

// ---------------- helpers ----------------------------------------------------
__device__ __forceinline__ void split2(float x, float y, uint32_t& hi, uint32_t& lo) {
    __nv_bfloat16 hx = __float2bfloat16(x);
    __nv_bfloat16 hy = __float2bfloat16(y);
    float rx = x - __bfloat162float(hx);
    float ry = y - __bfloat162float(hy);
    __nv_bfloat162 h;
    h.x = hx; h.y = hy;
    __nv_bfloat162 l = __floats2bfloat162_rn(rx, ry);
    hi = reinterpret_cast<uint32_t&>(h);
    lo = reinterpret_cast<uint32_t&>(l);
}

__device__ __forceinline__ void mma16816(float c[4], const uint32_t a[4], const uint32_t b[2]) {
    asm volatile(
        "mma.sync.aligned.m16n8k16.row.col.f32.bf16.bf16.f32 "
        "{%0,%1,%2,%3}, {%4,%5,%6,%7}, {%8,%9}, {%0,%1,%2,%3};"
        : "+f"(c[0]), "+f"(c[1]), "+f"(c[2]), "+f"(c[3])
        : "r"(a[0]), "r"(a[1]), "r"(a[2]), "r"(a[3]), "r"(b[0]), "r"(b[1]));
}

__device__ __forceinline__ void ldsm4(uint32_t r[4], uint32_t saddr) {
    asm volatile(
        "ldmatrix.sync.aligned.m8n8.x4.shared.b16 {%0,%1,%2,%3}, [%4];"
        : "=r"(r[0]), "=r"(r[1]), "=r"(r[2]), "=r"(r[3]) : "r"(saddr));
}

__device__ __forceinline__ void cpasync16(uint32_t smem, const void* gptr) {
    asm volatile("cp.async.cg.shared.global [%0], [%1], 16;" :: "r"(smem), "l"(gptr));
}
__device__ __forceinline__ void cp_commit() {
    asm volatile("cp.async.commit_group;");
}
template <int Nw>
__device__ __forceinline__ void cp_wait() {
    asm volatile("cp.async.wait_group %0;" :: "n"(Nw));
}

// ---------------- setup kernels ---------------------------------------------
__global__ void k_zero_deg() {
    int i = blockIdx.x * blockDim.x + threadIdx.x;
    if (i < NN) g_deg[i] = 0;
}

__global__ void k_count(const int* __restrict__ ei) {
    int e = blockIdx.x * blockDim.x + threadIdx.x;
    if (e < EE) atomicAdd(&g_deg[ei[EE + e]], 1);
}

__global__ void k_scan1() {
    __shared__ int s[1024];
    int t = threadIdx.x;
    int i = blockIdx.x * 1024 + t;
    s[t] = (i < NN) ? g_deg[i] : 0;
    __syncthreads();
    for (int off = 512; off; off >>= 1) {
        if (t < off) s[t] += s[t + off];
        __syncthreads();
    }
    if (t == 0) g_part[blockIdx.x] = s[0];
}

__global__ void k_scan2() {
    __shared__ int s[256];
    int t = threadIdx.x;
    int v = (t < SCB) ? g_part[t] : 0;
    s[t] = v;
    __syncthreads();
    for (int off = 1; off < 256; off <<= 1) {
        int u = (t >= off) ? s[t - off] : 0;
        __syncthreads();
        s[t] += u;
        __syncthreads();
    }
    if (t < SCB) g_part[t] = s[t] - v;
    if (t == 255) g_rowptr[NN] = s[255];
}

__global__ void k_scan3() {
    __shared__ int s[1024];
    int t = threadIdx.x;
    int i = blockIdx.x * 1024 + t;
    int d = (i < NN) ? g_deg[i] : 0;
    s[t] = d;
    __syncthreads();
    for (int off = 1; off < 1024; off <<= 1) {
        int u = (t >= off) ? s[t - off] : 0;
        __syncthreads();
        s[t] += u;
        __syncthreads();
    }
    if (i < NN) {
        int excl = s[t] - d + g_part[blockIdx.x];
        g_rowptr[i] = excl;
        g_cursor[i] = excl;
        g_dinv[i] = rsqrtf((float)(d + 1));
    }
}

__global__ void k_scatter(const int* __restrict__ ei) {
    int e = blockIdx.x * blockDim.x + threadIdx.x;
    if (e < EE) {
        int srcn = ei[e];
        int dstn = ei[EE + e];
        int pos = atomicAdd(&g_cursor[dstn], 1);
        g_edge[pos] = make_int2(srcn, __float_as_int(g_dinv[srcn] * g_dinv[dstn]));
    }
}

__global__ void k_split_w(const float* __restrict__ W1, const float* __restrict__ W2,
                          const float* __restrict__ W3, const float* __restrict__ Wc1,
                          const float* __restrict__ Wc2) {
    int p = blockIdx.x * blockDim.x + threadIdx.x;
    if (p >= WPAIRS) return;
    const float* src;
    int off, N, Kp;
    if (p < WOFF2)       { src = W1;  off = p - WOFF1;  N = 128; Kp = 64; }
    else if (p < WOFF3)  { src = W2;  off = p - WOFF2;  N = 128; Kp = 64; }
    else if (p < WOFFC1) { src = W3;  off = p - WOFF3;  N = 64;  Kp = 64; }
    else if (p < WOFFC2) { src = Wc1; off = p - WOFFC1; N = 128; Kp = 96; }
    else                 { src = Wc2; off = p - WOFFC2; N = 64;  Kp = 64; }
    int n = off / Kp, kp = off % Kp;
    float a = src[(size_t)(2 * kp) * N + n];
    float b = src[(size_t)(2 * kp + 1) * N + n];
    uint32_t h, l;
    split2(a, b, h, l);
    g_wh[p] = h;
    g_wl[p] = l;
}

__global__ void k_split_x(const float* __restrict__ x) {
    int i = blockIdx.x * blockDim.x + threadIdx.x;
    if (i >= NN * HF / 4) return;
    float4 v = ((const float4*)x)[i];
    uint32_t h0, l0, h1, l1;
    split2(v.x, v.y, h0, l0);
    split2(v.z, v.w, h1, l1);
    ((uint2*)g_aH)[i] = make_uint2(h0, h1);
    ((uint2*)g_aL)[i] = make_uint2(l0, l1);
}

// ---------------- bf16 split-MMA GEMM, cp.async double-buffered --------------
// OMODE: 0 = fp32 out, 1 = split bf16-pair out, 2 = half2 out.

#define BM 128
#define SA 20
#define SBS 20

template <int BNT, int OMODE, bool FUSE>
__global__ void __launch_bounds__(256)
k_mma(const uint32_t* __restrict__ Ah, const uint32_t* __restrict__ Al,
      int wOff, const float* __restrict__ bias,
      float* __restrict__ Cf, uint32_t* __restrict__ OutH, uint32_t* __restrict__ OutL,
      int M, int K) {
    constexpr int NT = BNT / 16;
    constexpr int AW = BM * SA;
    constexpr int BW = BNT * SBS;
    constexpr int SW = 2 * AW + 2 * BW;

    extern __shared__ uint32_t smem[];

    const int tid = threadIdx.x;
    const int wid = tid >> 5;
    const int lane = tid & 31;
    const int wm = wid & 3;
    const int wn = wid >> 2;
    const int gid = lane >> 2;
    const int tig = lane & 3;
    const int bm = blockIdx.y * BM;
    const int Kp = K >> 1;
    const int KT = Kp >> 4;

    const uint32_t smB = (uint32_t)__cvta_generic_to_shared(smem);

    float c[2][NT][4];
#pragma unroll
    for (int mt = 0; mt < 2; mt++)
#pragma unroll
        for (int nt = 0; nt < NT; nt++)
#pragma unroll
            for (int j = 0; j < 4; j++) c[mt][nt][j] = 0.f;

    const int aRow = lane & 15;
    const int aKh = (lane >> 4) * 4;
    const int bN = (lane >> 4) * 8 + (lane & 7);
    const int bKh = ((lane >> 3) & 1) * 4;

    auto prefetch = [&](int kt, int buf) {
        const int k0p = kt * 16;
        uint32_t base = smB + (uint32_t)buf * SW * 4u;
#pragma unroll
        for (int i = 0; i < 2; i++) {
            int task = tid + i * 256;
            int row = task >> 2;
            int qg = (task & 3) * 4;
            int gr = bm + row;
            if (gr >= M) gr = M - 1;
            size_t gofs = (size_t)gr * Kp + k0p + qg;
            uint32_t so = (uint32_t)(row * SA + qg) * 4u;
            cpasync16(base + so, &Ah[gofs]);
            cpasync16(base + AW * 4u + so, &Al[gofs]);
        }
#pragma unroll
        for (int i = 0; i < BNT / 64; i++) {
            int task = tid + i * 256;
            int n = task >> 2;
            int qg = (task & 3) * 4;
            size_t gofs = (size_t)wOff + (size_t)n * Kp + k0p + qg;
            uint32_t so = (uint32_t)(n * SBS + qg) * 4u;
            cpasync16(base + 2u * AW * 4u + so, &g_wh[gofs]);
            cpasync16(base + (2u * AW + BW) * 4u + so, &g_wl[gofs]);
        }
        cp_commit();
    };

    prefetch(0, 0);

    for (int kt = 0; kt < KT; kt++) {
        const int buf = kt & 1;
        if (kt + 1 < KT) {
            prefetch(kt + 1, buf ^ 1);
            cp_wait<1>();
        } else {
            cp_wait<0>();
        }
        __syncthreads();

        uint32_t sAhB = smB + (uint32_t)buf * SW * 4u;
        uint32_t sAlB = sAhB + AW * 4u;
        uint32_t sBhB = sAlB + AW * 4u;
        uint32_t sBlB = sBhB + BW * 4u;

#pragma unroll
        for (int ks = 0; ks < 2; ks++) {
            uint32_t ah[2][4], al[2][4];
#pragma unroll
            for (int mt = 0; mt < 2; mt++) {
                uint32_t woff = (uint32_t)((wm * 32 + mt * 16 + aRow) * SA + ks * 8 + aKh) * 4u;
                ldsm4(ah[mt], sAhB + woff);
                ldsm4(al[mt], sAlB + woff);
            }
            uint32_t bh[NT][2], bl[NT][2];
#pragma unroll
            for (int j = 0; j < NT / 2; j++) {
                uint32_t woff = (uint32_t)((wn * (BNT / 2) + j * 16 + bN) * SBS + ks * 8 + bKh) * 4u;
                uint32_t rh[4], rl[4];
                ldsm4(rh, sBhB + woff);
                ldsm4(rl, sBlB + woff);
                bh[2 * j][0] = rh[0]; bh[2 * j][1] = rh[1];
                bh[2 * j + 1][0] = rh[2]; bh[2 * j + 1][1] = rh[3];
                bl[2 * j][0] = rl[0]; bl[2 * j][1] = rl[1];
                bl[2 * j + 1][0] = rl[2]; bl[2 * j + 1][1] = rl[3];
            }
#pragma unroll
            for (int mt = 0; mt < 2; mt++)
#pragma unroll
                for (int nt = 0; nt < NT; nt++) {
                    mma16816(c[mt][nt], ah[mt], bh[nt]);
                    mma16816(c[mt][nt], ah[mt], bl[nt]);
                    mma16816(c[mt][nt], al[mt], bh[nt]);
                }
        }
        __syncthreads();
    }

    const int N = BNT;
#pragma unroll
    for (int mt = 0; mt < 2; mt++)
#pragma unroll
        for (int nt = 0; nt < NT; nt++) {
            int gr0 = bm + wm * 32 + mt * 16 + gid;
            int gc = wn * (BNT / 2) + nt * 8 + tig * 2;
            float v0 = c[mt][nt][0], v1 = c[mt][nt][1];
            float v2 = c[mt][nt][2], v3 = c[mt][nt][3];
            if (FUSE) {
                float b0 = bias[gc], b1 = bias[gc + 1];
                v0 = fmaxf(v0 + b0, 0.f);
                v1 = fmaxf(v1 + b1, 0.f);
                v2 = fmaxf(v2 + b0, 0.f);
                v3 = fmaxf(v3 + b1, 0.f);
            }
            if (OMODE == 1) {
                uint32_t h, l;
                if (gr0 < M) {
                    split2(v0, v1, h, l);
                    size_t p = (size_t)gr0 * (N >> 1) + (gc >> 1);
                    OutH[p] = h;
                    OutL[p] = l;
                }
                if (gr0 + 8 < M) {
                    split2(v2, v3, h, l);
                    size_t p = (size_t)(gr0 + 8) * (N >> 1) + (gc >> 1);
                    OutH[p] = h;
                    OutL[p] = l;
                }
            } else if (OMODE == 2) {
                if (gr0 < M) {
                    __half2 hv = __floats2half2_rn(v0, v1);
                    OutH[(size_t)gr0 * (N >> 1) + (gc >> 1)] = reinterpret_cast<uint32_t&>(hv);
                }
                if (gr0 + 8 < M) {
                    __half2 hv = __floats2half2_rn(v2, v3);
                    OutH[(size_t)(gr0 + 8) * (N >> 1) + (gc >> 1)] = reinterpret_cast<uint32_t&>(hv);
                }
            } else {
                if (gr0 < M) *(float2*)&Cf[(size_t)gr0 * N + gc] = make_float2(v0, v1);
                if (gr0 + 8 < M) *(float2*)&Cf[(size_t)(gr0 + 8) * N + gc] = make_float2(v2, v3);
            }
        }
}

// ---------------- fp16 gather aggregation, split-bf16 output -----------------
// h stored as half2 rows (F/2 uint32 per row). Accumulate fp32.
template <int F>
__global__ void k_agg(const uint32_t* __restrict__ h, const float* __restrict__ bias,
                      uint32_t* __restrict__ outH, uint32_t* __restrict__ outL) {
    int warp = (blockIdx.x * blockDim.x + threadIdx.x) >> 5;
    int lane = threadIdx.x & 31;
    if (warp >= NN) return;
    const int FP = F / 2;            // uint32 per row
    const int VPL = F / 32;          // floats per lane (4 or 2)
    float di = g_dinv[warp];
    float di2 = di * di;
    float acc[VPL];

    auto loadrow = [&](int row, float2& a, float2& b) {
        if (VPL == 4) {
            uint2 v = *(const uint2*)(h + (size_t)row * FP + lane * 2);
            a = __half22float2(reinterpret_cast<__half2&>(v.x));
            b = __half22float2(reinterpret_cast<__half2&>(v.y));
        } else {
            uint32_t v = h[(size_t)row * FP + lane];
            a = __half22float2(reinterpret_cast<__half2&>(v));
        }
    };

    {
        float2 a, b;
        loadrow(warp, a, b);
        acc[0] = a.x * di2;
        acc[1] = a.y * di2;
        if (VPL == 4) { acc[2] = b.x * di2; acc[3] = b.y * di2; }
    }

    int beg = g_rowptr[warp];
    int end = g_rowptr[warp + 1];
    int j = beg;
    for (; j + 1 < end; j += 2) {
        int2 e0 = g_edge[j];
        int2 e1 = g_edge[j + 1];
        float w0 = __int_as_float(e0.y);
        float w1 = __int_as_float(e1.y);
        float2 a0, b0, a1, b1;
        loadrow(e0.x, a0, b0);
        loadrow(e1.x, a1, b1);
        acc[0] += a0.x * w0; acc[1] += a0.y * w0;
        acc[0] += a1.x * w1; acc[1] += a1.y * w1;
        if (VPL == 4) {
            acc[2] += b0.x * w0; acc[3] += b0.y * w0;
            acc[2] += b1.x * w1; acc[3] += b1.y * w1;
        }
    }
    if (j < end) {
        int2 e0 = g_edge[j];
        float w0 = __int_as_float(e0.y);
        float2 a0, b0;
        loadrow(e0.x, a0, b0);
        acc[0] += a0.x * w0; acc[1] += a0.y * w0;
        if (VPL == 4) { acc[2] += b0.x * w0; acc[3] += b0.y * w0; }
    }

    if (VPL == 4) {
        float4 b = *(const float4*)&bias[lane * 4];
        float o0 = fmaxf(acc[0] + b.x, 0.f);
        float o1 = fmaxf(acc[1] + b.y, 0.f);
        float o2 = fmaxf(acc[2] + b.z, 0.f);
        float o3 = fmaxf(acc[3] + b.w, 0.f);
        uint32_t h0, l0, h1, l1;
        split2(o0, o1, h0, l0);
        split2(o2, o3, h1, l1);
        size_t p = (size_t)warp * FP + lane * 2;
        *(uint2*)&outH[p] = make_uint2(h0, h1);
        *(uint2*)&outL[p] = make_uint2(l0, l1);
    } else {
        float2 b = *(const float2*)&bias[lane * 2];
        float o0 = fmaxf(acc[0] + b.x, 0.f);
        float o1 = fmaxf(acc[1] + b.y, 0.f);
        uint32_t h0, l0;
        split2(o0, o1, h0, l0);
        size_t p = (size_t)warp * FP + lane;
        outH[p] = h0;
        outL[p] = l0;
    }
}

// ---------------- final 64->2 + log_softmax ----------------------------------
__global__ void k_final(const float* __restrict__ z, const float* __restrict__ Wc3,
                        const float* __restrict__ bc3, float* __restrict__ out) {
    __shared__ float sw[HF2 * 2];
    __shared__ float sb[2];
    if (threadIdx.x < HF2 * 2) sw[threadIdx.x] = Wc3[threadIdx.x];
    if (threadIdx.x < 2) sb[threadIdx.x] = bc3[threadIdx.x];
    __syncthreads();
    int g = blockIdx.x * blockDim.x + threadIdx.x;
    if (g >= BBG) return;
    const float* zr = z + (size_t)g * HF2;
    float a0 = sb[0], a1 = sb[1];
#pragma unroll
    for (int k = 0; k < HF2; k++) {
        float zv = zr[k];
        a0 += zv * sw[2 * k + 0];
        a1 += zv * sw[2 * k + 1];
    }
    float m = fmaxf(a0, a1);
    float l = logf(expf(a0 - m) + expf(a1 - m));
    out[2 * g + 0] = a0 - m - l;
    out[2 * g + 1] = a1 - m - l;
}

// ---------------- launch -----------------------------------------------------
extern "C" void kernel_launch(void* const* d_in, const int* in_sizes, int n_in,
                              void* d_out, int out_size) {
    const float* x   = (const float*)d_in[0];
    const int*   ei  = (const int*)d_in[1];
    const float* W1  = (const float*)d_in[2];
    const float* b1  = (const float*)d_in[3];
    const float* W2  = (const float*)d_in[4];
    const float* b2  = (const float*)d_in[5];
    const float* W3  = (const float*)d_in[6];
    const float* b3  = (const float*)d_in[7];
    const float* Wc1 = (const float*)d_in[8];
    const float* bc1 = (const float*)d_in[9];
    const float* Wc2 = (const float*)d_in[10];
    const float* bc2 = (const float*)d_in[11];
    const float* Wc3 = (const float*)d_in[12];
    const float* bc3 = (const float*)d_in[13];
    float* out = (float*)d_out;

    float* bufF;
    uint32_t* bufH;
    uint32_t* aH;
    uint32_t* aL;
    cudaGetSymbolAddress((void**)&bufF, g_bufF);
    cudaGetSymbolAddress((void**)&bufH, g_bufH);
    cudaGetSymbolAddress((void**)&aH, g_aH);
    cudaGetSymbolAddress((void**)&aL, g_aL);

    const int SM128 = 2 * (2 * BM * SA + 2 * 128 * SBS) * 4;   // 81920
    const int SM64  = 2 * (2 * BM * SA + 2 * 64 * SBS) * 4;    // 61440
    static bool attrDone = false;
    if (!attrDone) {
        cudaFuncSetAttribute(k_mma<128, 2, false>, cudaFuncAttributeMaxDynamicSharedMemorySize, SM128);
        cudaFuncSetAttribute(k_mma<64, 2, false>,  cudaFuncAttributeMaxDynamicSharedMemorySize, SM64);
        cudaFuncSetAttribute(k_mma<128, 1, true>,  cudaFuncAttributeMaxDynamicSharedMemorySize, SM128);
        cudaFuncSetAttribute(k_mma<64, 0, true>,   cudaFuncAttributeMaxDynamicSharedMemorySize, SM64);
        attrDone = true;
    }

    // --- preprocessing ---
    k_zero_deg<<<(NN + 255) / 256, 256>>>();
    k_count<<<(EE + 255) / 256, 256>>>(ei);
    k_scan1<<<SCB, 1024>>>();
    k_scan2<<<1, 256>>>();
    k_scan3<<<SCB, 1024>>>();
    k_scatter<<<(EE + 255) / 256, 256>>>(ei);
    k_split_w<<<(WPAIRS + 255) / 256, 256>>>(W1, W2, W3, Wc1, Wc2);
    k_split_x<<<(NN * HF / 4 + 255) / 256, 256>>>(x);

    const int aggBlocks = (NN * 32 + 255) / 256;
    dim3 gN(1, (NN + BM - 1) / BM);
    dim3 gC(1, (BBG + BM - 1) / BM);

    // layer 1
    k_mma<128, 2, false><<<gN, 256, SM128>>>(aH, aL, WOFF1, nullptr, nullptr, bufH, nullptr, NN, HF);
    k_agg<HF><<<aggBlocks, 256>>>(bufH, b1, aH, aL);
    // layer 2
    k_mma<128, 2, false><<<gN, 256, SM128>>>(aH, aL, WOFF2, nullptr, nullptr, bufH, nullptr, NN, HF);
    k_agg<HF><<<aggBlocks, 256>>>(bufH, b2, aH, aL);
    // layer 3 (128 -> 64)
    k_mma<64, 2, false><<<gN, 256, SM64>>>(aH, aL, WOFF3, nullptr, nullptr, bufH, nullptr, NN, HF);
    k_agg<HF2><<<aggBlocks, 256>>>(bufH, b3, aH, aL);
    // classifier: input viewed as [50000, 192] (96 pairs/row)
    k_mma<128, 1, true><<<gC, 256, SM128>>>(aH, aL, WOFFC1, bc1, nullptr, aH + COFF, aL + COFF, BBG, 3 * HF2);
    k_mma<64, 0, true><<<gC, 256, SM64>>>(aH + COFF, aL + COFF, WOFFC2, bc2, bufF, nullptr, nullptr, BBG, HF);
    // final 64->2 + log_softmax
    k_final<<<(BBG + 255) / 256, 256>>>(bufF, Wc3, bc3, out);
}

// round 9
// speedup vs baseline: 1.8757x; 1.0104x over previous
#include <cuda_runtime.h>
#include <cuda_bf16.h>
#include <cuda_fp16.h>
#include <stdint.h>
#include <math.h>

#define NN 150000
#define EE 2400000
#define BBG 50000
#define HF 128
#define HF2 64

#define WOFF1  0
#define WOFF2  8192
#define WOFF3  16384
#define WOFFC1 20480
#define WOFFC2 32768
#define WPAIRS 36864

#define COFF   4800000   // classifier intermediate offset in pair buffers
#define SCB    147       // scan blocks: ceil(150000/1024)

// ---------------- scratch (static device globals; no allocation) -------------
__device__ float    g_bufF[(size_t)BBG * HF2];        // fp32 (classifier c2 out)
__device__ uint32_t g_bufH[(size_t)NN * HF / 2];      // half2 GEMM outputs (agg input)
__device__ uint32_t g_aH[(size_t)NN * HF / 2];        // split activations hi (bf162 pairs)
__device__ uint32_t g_aL[(size_t)NN * HF / 2];        // split activations lo
__device__ uint32_t g_wh[WPAIRS];
__device__ uint32_t g_wl[WPAIRS];
__device__ float g_dinv[NN];
__device__ int2  g_edge[EE];                          // {src, weight-as-int}
__device__ int   g_deg[NN];
__device__ int   g_rowptr[NN + 1];
__device__ int   g_cursor[NN];
__device__ int   g_part[256];

// ---------------- helpers ----------------------------------------------------
__device__ __forceinline__ void split2(float x, float y, uint32_t& hi, uint32_t& lo) {
    __nv_bfloat16 hx = __float2bfloat16(x);
    __nv_bfloat16 hy = __float2bfloat16(y);
    float rx = x - __bfloat162float(hx);
    float ry = y - __bfloat162float(hy);
    __nv_bfloat162 h;
    h.x = hx; h.y = hy;
    __nv_bfloat162 l = __floats2bfloat162_rn(rx, ry);
    hi = reinterpret_cast<uint32_t&>(h);
    lo = reinterpret_cast<uint32_t&>(l);
}

__device__ __forceinline__ void mma16816(float c[4], const uint32_t a[4], const uint32_t b[2]) {
    asm volatile(
        "mma.sync.aligned.m16n8k16.row.col.f32.bf16.bf16.f32 "
        "{%0,%1,%2,%3}, {%4,%5,%6,%7}, {%8,%9}, {%0,%1,%2,%3};"
        : "+f"(c[0]), "+f"(c[1]), "+f"(c[2]), "+f"(c[3])
        : "r"(a[0]), "r"(a[1]), "r"(a[2]), "r"(a[3]), "r"(b[0]), "r"(b[1]));
}

__device__ __forceinline__ void ldsm4(uint32_t r[4], uint32_t saddr) {
    asm volatile(
        "ldmatrix.sync.aligned.m8n8.x4.shared.b16 {%0,%1,%2,%3}, [%4];"
        : "=r"(r[0]), "=r"(r[1]), "=r"(r[2]), "=r"(r[3]) : "r"(saddr));
}

__device__ __forceinline__ void cpasync16(uint32_t smem, const void* gptr) {
    asm volatile("cp.async.cg.shared.global [%0], [%1], 16;" :: "r"(smem), "l"(gptr));
}
__device__ __forceinline__ void cp_commit() {
    asm volatile("cp.async.commit_group;");
}
template <int Nw>
__device__ __forceinline__ void cp_wait() {
    asm volatile("cp.async.wait_group %0;" :: "n"(Nw));
}

// ---------------- setup kernels ---------------------------------------------
__global__ void k_zero_deg() {
    int i = blockIdx.x * blockDim.x + threadIdx.x;
    if (i < NN) g_deg[i] = 0;
}

__global__ void k_count(const int* __restrict__ ei) {
    int e = blockIdx.x * blockDim.x + threadIdx.x;
    if (e < EE) atomicAdd(&g_deg[ei[EE + e]], 1);
}

__global__ void k_scan1() {
    __shared__ int s[1024];
    int t = threadIdx.x;
    int i = blockIdx.x * 1024 + t;
    s[t] = (i < NN) ? g_deg[i] : 0;
    __syncthreads();
    for (int off = 512; off; off >>= 1) {
        if (t < off) s[t] += s[t + off];
        __syncthreads();
    }
    if (t == 0) g_part[blockIdx.x] = s[0];
}

__global__ void k_scan2() {
    __shared__ int s[256];
    int t = threadIdx.x;
    int v = (t < SCB) ? g_part[t] : 0;
    s[t] = v;
    __syncthreads();
    for (int off = 1; off < 256; off <<= 1) {
        int u = (t >= off) ? s[t - off] : 0;
        __syncthreads();
        s[t] += u;
        __syncthreads();
    }
    if (t < SCB) g_part[t] = s[t] - v;
    if (t == 255) g_rowptr[NN] = s[255];
}

__global__ void k_scan3() {
    __shared__ int s[1024];
    int t = threadIdx.x;
    int i = blockIdx.x * 1024 + t;
    int d = (i < NN) ? g_deg[i] : 0;
    s[t] = d;
    __syncthreads();
    for (int off = 1; off < 1024; off <<= 1) {
        int u = (t >= off) ? s[t - off] : 0;
        __syncthreads();
        s[t] += u;
        __syncthreads();
    }
    if (i < NN) {
        int excl = s[t] - d + g_part[blockIdx.x];
        g_rowptr[i] = excl;
        g_cursor[i] = excl;
        g_dinv[i] = rsqrtf((float)(d + 1));
    }
}

__global__ void k_scatter(const int* __restrict__ ei) {
    int e = blockIdx.x * blockDim.x + threadIdx.x;
    if (e < EE) {
        int srcn = ei[e];
        int dstn = ei[EE + e];
        int pos = atomicAdd(&g_cursor[dstn], 1);
        g_edge[pos] = make_int2(srcn, __float_as_int(g_dinv[srcn] * g_dinv[dstn]));
    }
}

__global__ void k_split_w(const float* __restrict__ W1, const float* __restrict__ W2,
                          const float* __restrict__ W3, const float* __restrict__ Wc1,
                          const float* __restrict__ Wc2) {
    int p = blockIdx.x * blockDim.x + threadIdx.x;
    if (p >= WPAIRS) return;
    const float* src;
    int off, N, Kp;
    if (p < WOFF2)       { src = W1;  off = p - WOFF1;  N = 128; Kp = 64; }
    else if (p < WOFF3)  { src = W2;  off = p - WOFF2;  N = 128; Kp = 64; }
    else if (p < WOFFC1) { src = W3;  off = p - WOFF3;  N = 64;  Kp = 64; }
    else if (p < WOFFC2) { src = Wc1; off = p - WOFFC1; N = 128; Kp = 96; }
    else                 { src = Wc2; off = p - WOFFC2; N = 64;  Kp = 64; }
    int n = off / Kp, kp = off % Kp;
    float a = src[(size_t)(2 * kp) * N + n];
    float b = src[(size_t)(2 * kp + 1) * N + n];
    uint32_t h, l;
    split2(a, b, h, l);
    g_wh[p] = h;
    g_wl[p] = l;
}

__global__ void k_split_x(const float* __restrict__ x) {
    int i = blockIdx.x * blockDim.x + threadIdx.x;
    if (i >= NN * HF / 4) return;
    float4 v = ((const float4*)x)[i];
    uint32_t h0, l0, h1, l1;
    split2(v.x, v.y, h0, l0);
    split2(v.z, v.w, h1, l1);
    ((uint2*)g_aH)[i] = make_uint2(h0, h1);
    ((uint2*)g_aL)[i] = make_uint2(l0, l1);
}

// ---------------- bf16 split-MMA GEMM, cp.async double-buffered --------------
// OMODE: 0 = fp32 out, 1 = split bf16-pair out, 2 = half2 out.

#define BM 128
#define SA 20
#define SBS 20

template <int BNT, int OMODE, bool FUSE>
__global__ void __launch_bounds__(256)
k_mma(const uint32_t* __restrict__ Ah, const uint32_t* __restrict__ Al,
      int wOff, const float* __restrict__ bias,
      float* __restrict__ Cf, uint32_t* __restrict__ OutH, uint32_t* __restrict__ OutL,
      int M, int K) {
    constexpr int NT = BNT / 16;
    constexpr int AW = BM * SA;
    constexpr int BW = BNT * SBS;
    constexpr int SW = 2 * AW + 2 * BW;

    extern __shared__ uint32_t smem[];

    const int tid = threadIdx.x;
    const int wid = tid >> 5;
    const int lane = tid & 31;
    const int wm = wid & 3;
    const int wn = wid >> 2;
    const int gid = lane >> 2;
    const int tig = lane & 3;
    const int bm = blockIdx.y * BM;
    const int Kp = K >> 1;
    const int KT = Kp >> 4;

    const uint32_t smB = (uint32_t)__cvta_generic_to_shared(smem);

    float c[2][NT][4];
#pragma unroll
    for (int mt = 0; mt < 2; mt++)
#pragma unroll
        for (int nt = 0; nt < NT; nt++)
#pragma unroll
            for (int j = 0; j < 4; j++) c[mt][nt][j] = 0.f;

    const int aRow = lane & 15;
    const int aKh = (lane >> 4) * 4;
    const int bN = (lane >> 4) * 8 + (lane & 7);
    const int bKh = ((lane >> 3) & 1) * 4;

    auto prefetch = [&](int kt, int buf) {
        const int k0p = kt * 16;
        uint32_t base = smB + (uint32_t)buf * SW * 4u;
#pragma unroll
        for (int i = 0; i < 2; i++) {
            int task = tid + i * 256;
            int row = task >> 2;
            int qg = (task & 3) * 4;
            int gr = bm + row;
            if (gr >= M) gr = M - 1;
            size_t gofs = (size_t)gr * Kp + k0p + qg;
            uint32_t so = (uint32_t)(row * SA + qg) * 4u;
            cpasync16(base + so, &Ah[gofs]);
            cpasync16(base + AW * 4u + so, &Al[gofs]);
        }
#pragma unroll
        for (int i = 0; i < BNT / 64; i++) {
            int task = tid + i * 256;
            int n = task >> 2;
            int qg = (task & 3) * 4;
            size_t gofs = (size_t)wOff + (size_t)n * Kp + k0p + qg;
            uint32_t so = (uint32_t)(n * SBS + qg) * 4u;
            cpasync16(base + 2u * AW * 4u + so, &g_wh[gofs]);
            cpasync16(base + (2u * AW + BW) * 4u + so, &g_wl[gofs]);
        }
        cp_commit();
    };

    prefetch(0, 0);

    for (int kt = 0; kt < KT; kt++) {
        const int buf = kt & 1;
        if (kt + 1 < KT) {
            prefetch(kt + 1, buf ^ 1);
            cp_wait<1>();
        } else {
            cp_wait<0>();
        }
        __syncthreads();

        uint32_t sAhB = smB + (uint32_t)buf * SW * 4u;
        uint32_t sAlB = sAhB + AW * 4u;
        uint32_t sBhB = sAlB + AW * 4u;
        uint32_t sBlB = sBhB + BW * 4u;

#pragma unroll
        for (int ks = 0; ks < 2; ks++) {
            uint32_t ah[2][4], al[2][4];
#pragma unroll
            for (int mt = 0; mt < 2; mt++) {
                uint32_t woff = (uint32_t)((wm * 32 + mt * 16 + aRow) * SA + ks * 8 + aKh) * 4u;
                ldsm4(ah[mt], sAhB + woff);
                ldsm4(al[mt], sAlB + woff);
            }
            uint32_t bh[NT][2], bl[NT][2];
#pragma unroll
            for (int j = 0; j < NT / 2; j++) {
                uint32_t woff = (uint32_t)((wn * (BNT / 2) + j * 16 + bN) * SBS + ks * 8 + bKh) * 4u;
                uint32_t rh[4], rl[4];
                ldsm4(rh, sBhB + woff);
                ldsm4(rl, sBlB + woff);
                bh[2 * j][0] = rh[0]; bh[2 * j][1] = rh[1];
                bh[2 * j + 1][0] = rh[2]; bh[2 * j + 1][1] = rh[3];
                bl[2 * j][0] = rl[0]; bl[2 * j][1] = rl[1];
                bl[2 * j + 1][0] = rl[2]; bl[2 * j + 1][1] = rl[3];
            }
#pragma unroll
            for (int mt = 0; mt < 2; mt++)
#pragma unroll
                for (int nt = 0; nt < NT; nt++) {
                    mma16816(c[mt][nt], ah[mt], bh[nt]);
                    mma16816(c[mt][nt], ah[mt], bl[nt]);
                    mma16816(c[mt][nt], al[mt], bh[nt]);
                }
        }
        __syncthreads();
    }

    const int N = BNT;
#pragma unroll
    for (int mt = 0; mt < 2; mt++)
#pragma unroll
        for (int nt = 0; nt < NT; nt++) {
            int gr0 = bm + wm * 32 + mt * 16 + gid;
            int gc = wn * (BNT / 2) + nt * 8 + tig * 2;
            float v0 = c[mt][nt][0], v1 = c[mt][nt][1];
            float v2 = c[mt][nt][2], v3 = c[mt][nt][3];
            if (FUSE) {
                float b0 = bias[gc], b1 = bias[gc + 1];
                v0 = fmaxf(v0 + b0, 0.f);
                v1 = fmaxf(v1 + b1, 0.f);
                v2 = fmaxf(v2 + b0, 0.f);
                v3 = fmaxf(v3 + b1, 0.f);
            }
            if (OMODE == 1) {
                uint32_t h, l;
                if (gr0 < M) {
                    split2(v0, v1, h, l);
                    size_t p = (size_t)gr0 * (N >> 1) + (gc >> 1);
                    OutH[p] = h;
                    OutL[p] = l;
                }
                if (gr0 + 8 < M) {
                    split2(v2, v3, h, l);
                    size_t p = (size_t)(gr0 + 8) * (N >> 1) + (gc >> 1);
                    OutH[p] = h;
                    OutL[p] = l;
                }
            } else if (OMODE == 2) {
                if (gr0 < M) {
                    __half2 hv = __floats2half2_rn(v0, v1);
                    OutH[(size_t)gr0 * (N >> 1) + (gc >> 1)] = reinterpret_cast<uint32_t&>(hv);
                }
                if (gr0 + 8 < M) {
                    __half2 hv = __floats2half2_rn(v2, v3);
                    OutH[(size_t)(gr0 + 8) * (N >> 1) + (gc >> 1)] = reinterpret_cast<uint32_t&>(hv);
                }
            } else {
                if (gr0 < M) *(float2*)&Cf[(size_t)gr0 * N + gc] = make_float2(v0, v1);
                if (gr0 + 8 < M) *(float2*)&Cf[(size_t)(gr0 + 8) * N + gc] = make_float2(v2, v3);
            }
        }
}

// ---------------- fp16 gather aggregation, split-bf16 output -----------------
template <int F>
__global__ void k_agg(const uint32_t* __restrict__ h, const float* __restrict__ bias,
                      uint32_t* __restrict__ outH, uint32_t* __restrict__ outL) {
    int warp = (blockIdx.x * blockDim.x + threadIdx.x) >> 5;
    int lane = threadIdx.x & 31;
    if (warp >= NN) return;
    const int FP = F / 2;
    const int VPL = F / 32;
    float di = g_dinv[warp];
    float di2 = di * di;
    float acc[VPL];

    auto loadrow = [&](int row, float2& a, float2& b) {
        if (VPL == 4) {
            uint2 v = *(const uint2*)(h + (size_t)row * FP + lane * 2);
            a = __half22float2(reinterpret_cast<__half2&>(v.x));
            b = __half22float2(reinterpret_cast<__half2&>(v.y));
        } else {
            uint32_t v = h[(size_t)row * FP + lane];
            a = __half22float2(reinterpret_cast<__half2&>(v));
        }
    };

    {
        float2 a, b;
        loadrow(warp, a, b);
        acc[0] = a.x * di2;
        acc[1] = a.y * di2;
        if (VPL == 4) { acc[2] = b.x * di2; acc[3] = b.y * di2; }
    }

    int beg = g_rowptr[warp];
    int end = g_rowptr[warp + 1];
    int j = beg;
    for (; j + 3 < end; j += 4) {
        int2 e0 = g_edge[j];
        int2 e1 = g_edge[j + 1];
        int2 e2 = g_edge[j + 2];
        int2 e3 = g_edge[j + 3];
        float w0 = __int_as_float(e0.y);
        float w1 = __int_as_float(e1.y);
        float w2 = __int_as_float(e2.y);
        float w3 = __int_as_float(e3.y);
        float2 a0, b0, a1, b1, a2, b2, a3, b3;
        loadrow(e0.x, a0, b0);
        loadrow(e1.x, a1, b1);
        loadrow(e2.x, a2, b2);
        loadrow(e3.x, a3, b3);
        acc[0] += a0.x * w0; acc[1] += a0.y * w0;
        acc[0] += a1.x * w1; acc[1] += a1.y * w1;
        acc[0] += a2.x * w2; acc[1] += a2.y * w2;
        acc[0] += a3.x * w3; acc[1] += a3.y * w3;
        if (VPL == 4) {
            acc[2] += b0.x * w0; acc[3] += b0.y * w0;
            acc[2] += b1.x * w1; acc[3] += b1.y * w1;
            acc[2] += b2.x * w2; acc[3] += b2.y * w2;
            acc[2] += b3.x * w3; acc[3] += b3.y * w3;
        }
    }
    for (; j < end; j++) {
        int2 e0 = g_edge[j];
        float w0 = __int_as_float(e0.y);
        float2 a0, b0;
        loadrow(e0.x, a0, b0);
        acc[0] += a0.x * w0; acc[1] += a0.y * w0;
        if (VPL == 4) { acc[2] += b0.x * w0; acc[3] += b0.y * w0; }
    }

    if (VPL == 4) {
        float4 b = *(const float4*)&bias[lane * 4];
        float o0 = fmaxf(acc[0] + b.x, 0.f);
        float o1 = fmaxf(acc[1] + b.y, 0.f);
        float o2 = fmaxf(acc[2] + b.z, 0.f);
        float o3 = fmaxf(acc[3] + b.w, 0.f);
        uint32_t h0, l0, h1, l1;
        split2(o0, o1, h0, l0);
        split2(o2, o3, h1, l1);
        size_t p = (size_t)warp * FP + lane * 2;
        *(uint2*)&outH[p] = make_uint2(h0, h1);
        *(uint2*)&outL[p] = make_uint2(l0, l1);
    } else {
        float2 b = *(const float2*)&bias[lane * 2];
        float o0 = fmaxf(acc[0] + b.x, 0.f);
        float o1 = fmaxf(acc[1] + b.y, 0.f);
        uint32_t h0, l0;
        split2(o0, o1, h0, l0);
        size_t p = (size_t)warp * FP + lane;
        outH[p] = h0;
        outL[p] = l0;
    }
}

// ---------------- final 64->2 + log_softmax ----------------------------------
__global__ void k_final(const float* __restrict__ z, const float* __restrict__ Wc3,
                        const float* __restrict__ bc3, float* __restrict__ out) {
    __shared__ float sw[HF2 * 2];
    __shared__ float sb[2];
    if (threadIdx.x < HF2 * 2) sw[threadIdx.x] = Wc3[threadIdx.x];
    if (threadIdx.x < 2) sb[threadIdx.x] = bc3[threadIdx.x];
    __syncthreads();
    int g = blockIdx.x * blockDim.x + threadIdx.x;
    if (g >= BBG) return;
    const float* zr = z + (size_t)g * HF2;
    float a0 = sb[0], a1 = sb[1];
#pragma unroll
    for (int k = 0; k < HF2; k++) {
        float zv = zr[k];
        a0 += zv * sw[2 * k + 0];
        a1 += zv * sw[2 * k + 1];
    }
    float m = fmaxf(a0, a1);
    float l = logf(expf(a0 - m) + expf(a1 - m));
    out[2 * g + 0] = a0 - m - l;
    out[2 * g + 1] = a1 - m - l;
}

// ---------------- launch -----------------------------------------------------
extern "C" void kernel_launch(void* const* d_in, const int* in_sizes, int n_in,
                              void* d_out, int out_size) {
    const float* x   = (const float*)d_in[0];
    const int*   ei  = (const int*)d_in[1];
    const float* W1  = (const float*)d_in[2];
    const float* b1  = (const float*)d_in[3];
    const float* W2  = (const float*)d_in[4];
    const float* b2  = (const float*)d_in[5];
    const float* W3  = (const float*)d_in[6];
    const float* b3  = (const float*)d_in[7];
    const float* Wc1 = (const float*)d_in[8];
    const float* bc1 = (const float*)d_in[9];
    const float* Wc2 = (const float*)d_in[10];
    const float* bc2 = (const float*)d_in[11];
    const float* Wc3 = (const float*)d_in[12];
    const float* bc3 = (const float*)d_in[13];
    float* out = (float*)d_out;

    float* bufF;
    uint32_t* bufH;
    uint32_t* aH;
    uint32_t* aL;
    cudaGetSymbolAddress((void**)&bufF, g_bufF);
    cudaGetSymbolAddress((void**)&bufH, g_bufH);
    cudaGetSymbolAddress((void**)&aH, g_aH);
    cudaGetSymbolAddress((void**)&aL, g_aL);

    const int SM128 = 2 * (2 * BM * SA + 2 * 128 * SBS) * 4;   // 81920
    const int SM64  = 2 * (2 * BM * SA + 2 * 64 * SBS) * 4;    // 61440
    static bool attrDone = false;
    if (!attrDone) {
        cudaFuncSetAttribute(k_mma<128, 2, false>, cudaFuncAttributeMaxDynamicSharedMemorySize, SM128);
        cudaFuncSetAttribute(k_mma<64, 2, false>,  cudaFuncAttributeMaxDynamicSharedMemorySize, SM64);
        cudaFuncSetAttribute(k_mma<128, 1, true>,  cudaFuncAttributeMaxDynamicSharedMemorySize, SM128);
        cudaFuncSetAttribute(k_mma<64, 0, true>,   cudaFuncAttributeMaxDynamicSharedMemorySize, SM64);
        attrDone = true;
    }

    // side stream + events (created once; host-side only)
    static cudaStream_t sB = nullptr;
    static cudaEvent_t evFork = nullptr, evJoin = nullptr;
    if (sB == nullptr) {
        cudaStreamCreateWithFlags(&sB, cudaStreamNonBlocking);
        cudaEventCreateWithFlags(&evFork, cudaEventDisableTiming);
        cudaEventCreateWithFlags(&evJoin, cudaEventDisableTiming);
    }

    const int aggBlocks = (NN * 32 + 255) / 256;
    dim3 gN(1, (NN + BM - 1) / BM);
    dim3 gC(1, (BBG + BM - 1) / BM);

    // --- fork: stream B does split path + layer-1 GEMM ---
    cudaEventRecord(evFork, 0);
    cudaStreamWaitEvent(sB, evFork, 0);
    k_split_w<<<(WPAIRS + 255) / 256, 256, 0, sB>>>(W1, W2, W3, Wc1, Wc2);
    k_split_x<<<(NN * HF / 4 + 255) / 256, 256, 0, sB>>>(x);
    k_mma<128, 2, false><<<gN, 256, SM128, sB>>>(aH, aL, WOFF1, nullptr, nullptr, bufH, nullptr, NN, HF);
    cudaEventRecord(evJoin, sB);

    // --- default stream: CSR build ---
    k_zero_deg<<<(NN + 255) / 256, 256>>>();
    k_count<<<(EE + 255) / 256, 256>>>(ei);
    k_scan1<<<SCB, 1024>>>();
    k_scan2<<<1, 256>>>();
    k_scan3<<<SCB, 1024>>>();
    k_scatter<<<(EE + 255) / 256, 256>>>(ei);

    // --- join ---
    cudaStreamWaitEvent(0, evJoin, 0);

    // layer 1 agg
    k_agg<HF><<<aggBlocks, 256>>>(bufH, b1, aH, aL);
    // layer 2
    k_mma<128, 2, false><<<gN, 256, SM128>>>(aH, aL, WOFF2, nullptr, nullptr, bufH, nullptr, NN, HF);
    k_agg<HF><<<aggBlocks, 256>>>(bufH, b2, aH, aL);
    // layer 3 (128 -> 64)
    k_mma<64, 2, false><<<gN, 256, SM64>>>(aH, aL, WOFF3, nullptr, nullptr, bufH, nullptr, NN, HF);
    k_agg<HF2><<<aggBlocks, 256>>>(bufH, b3, aH, aL);
    // classifier: input viewed as [50000, 192] (96 pairs/row)
    k_mma<128, 1, true><<<gC, 256, SM128>>>(aH, aL, WOFFC1, bc1, nullptr, aH + COFF, aL + COFF, BBG, 3 * HF2);
    k_mma<64, 0, true><<<gC, 256, SM64>>>(aH + COFF, aL + COFF, WOFFC2, bc2, bufF, nullptr, nullptr, BBG, HF);
    // final 64->2 + log_softmax
    k_final<<<(BBG + 255) / 256, 256>>>(bufF, Wc3, bc3, out);
}

// round 10
// speedup vs baseline: 2.2318x; 1.1898x over previous
#include <cuda_runtime.h>
#include <cuda_bf16.h>
#include <stdint.h>
#include <math.h>

#define NN 150000
#define EE 2400000
#define BBG 50000
#define HF 128
#define HF2 64

#define WOFF1  0
#define WOFF2  8192
#define WOFF3  16384
#define WOFFC1 20480
#define WOFFC2 32768
#define WPAIRS 36864

#define COFF   4800000   // classifier intermediate offset in aH (words)
#define SCB    147       // scan blocks: ceil(150000/1024)

// ---------------- scratch (static device globals; no allocation) -------------
__device__ float    g_bufF[(size_t)BBG * HF2];        // fp32 (classifier c2 out)
__device__ uint32_t g_bufH[(size_t)NN * HF / 2];      // bf162 GEMM outputs (agg input)
__device__ uint32_t g_aH[(size_t)NN * HF / 2];        // bf162 activations (GEMM input)
__device__ uint32_t g_wh[WPAIRS];                     // bf162 weights, n-major [n][k/2]
__device__ float g_dinv[NN];
__device__ int2  g_edge[EE];                          // {src, weight-as-int}
__device__ int   g_deg[NN];
__device__ int   g_rowptr[NN + 1];
__device__ int   g_cursor[NN];
__device__ int   g_part[256];

// ---------------- helpers ----------------------------------------------------
__device__ __forceinline__ uint32_t cvt2(float x, float y) {
    __nv_bfloat162 h = __floats2bfloat162_rn(x, y);
    return reinterpret_cast<uint32_t&>(h);
}

__device__ __forceinline__ void mma16816(float c[4], const uint32_t a[4], const uint32_t b[2]) {
    asm volatile(
        "mma.sync.aligned.m16n8k16.row.col.f32.bf16.bf16.f32 "
        "{%0,%1,%2,%3}, {%4,%5,%6,%7}, {%8,%9}, {%0,%1,%2,%3};"
        : "+f"(c[0]), "+f"(c[1]), "+f"(c[2]), "+f"(c[3])
        : "r"(a[0]), "r"(a[1]), "r"(a[2]), "r"(a[3]), "r"(b[0]), "r"(b[1]));
}

__device__ __forceinline__ void ldsm4(uint32_t r[4], uint32_t saddr) {
    asm volatile(
        "ldmatrix.sync.aligned.m8n8.x4.shared.b16 {%0,%1,%2,%3}, [%4];"
        : "=r"(r[0]), "=r"(r[1]), "=r"(r[2]), "=r"(r[3]) : "r"(saddr));
}

__device__ __forceinline__ void cpasync16(uint32_t smem, const void* gptr) {
    asm volatile("cp.async.cg.shared.global [%0], [%1], 16;" :: "r"(smem), "l"(gptr));
}
__device__ __forceinline__ void cp_commit() {
    asm volatile("cp.async.commit_group;");
}
template <int Nw>
__device__ __forceinline__ void cp_wait() {
    asm volatile("cp.async.wait_group %0;" :: "n"(Nw));
}

// ---------------- setup kernels ---------------------------------------------
__global__ void k_zero_deg() {
    int i = blockIdx.x * blockDim.x + threadIdx.x;
    if (i < NN) g_deg[i] = 0;
}

__global__ void k_count(const int* __restrict__ ei) {
    int e = blockIdx.x * blockDim.x + threadIdx.x;
    if (e < EE) atomicAdd(&g_deg[ei[EE + e]], 1);
}

__global__ void k_scan1() {
    __shared__ int s[1024];
    int t = threadIdx.x;
    int i = blockIdx.x * 1024 + t;
    s[t] = (i < NN) ? g_deg[i] : 0;
    __syncthreads();
    for (int off = 512; off; off >>= 1) {
        if (t < off) s[t] += s[t + off];
        __syncthreads();
    }
    if (t == 0) g_part[blockIdx.x] = s[0];
}

__global__ void k_scan2() {
    __shared__ int s[256];
    int t = threadIdx.x;
    int v = (t < SCB) ? g_part[t] : 0;
    s[t] = v;
    __syncthreads();
    for (int off = 1; off < 256; off <<= 1) {
        int u = (t >= off) ? s[t - off] : 0;
        __syncthreads();
        s[t] += u;
        __syncthreads();
    }
    if (t < SCB) g_part[t] = s[t] - v;
    if (t == 255) g_rowptr[NN] = s[255];
}

__global__ void k_scan3() {
    __shared__ int s[1024];
    int t = threadIdx.x;
    int i = blockIdx.x * 1024 + t;
    int d = (i < NN) ? g_deg[i] : 0;
    s[t] = d;
    __syncthreads();
    for (int off = 1; off < 1024; off <<= 1) {
        int u = (t >= off) ? s[t - off] : 0;
        __syncthreads();
        s[t] += u;
        __syncthreads();
    }
    if (i < NN) {
        int excl = s[t] - d + g_part[blockIdx.x];
        g_rowptr[i] = excl;
        g_cursor[i] = excl;
        g_dinv[i] = rsqrtf((float)(d + 1));
    }
}

__global__ void k_scatter(const int* __restrict__ ei) {
    int e = blockIdx.x * blockDim.x + threadIdx.x;
    if (e < EE) {
        int srcn = ei[e];
        int dstn = ei[EE + e];
        int pos = atomicAdd(&g_cursor[dstn], 1);
        g_edge[pos] = make_int2(srcn, __float_as_int(g_dinv[srcn] * g_dinv[dstn]));
    }
}

// convert weights once, n-major layout: wT[n][k/2] bf162 pairs
__global__ void k_split_w(const float* __restrict__ W1, const float* __restrict__ W2,
                          const float* __restrict__ W3, const float* __restrict__ Wc1,
                          const float* __restrict__ Wc2) {
    int p = blockIdx.x * blockDim.x + threadIdx.x;
    if (p >= WPAIRS) return;
    const float* src;
    int off, N, Kp;
    if (p < WOFF2)       { src = W1;  off = p - WOFF1;  N = 128; Kp = 64; }
    else if (p < WOFF3)  { src = W2;  off = p - WOFF2;  N = 128; Kp = 64; }
    else if (p < WOFFC1) { src = W3;  off = p - WOFF3;  N = 64;  Kp = 64; }
    else if (p < WOFFC2) { src = Wc1; off = p - WOFFC1; N = 128; Kp = 96; }
    else                 { src = Wc2; off = p - WOFFC2; N = 64;  Kp = 64; }
    int n = off / Kp, kp = off % Kp;
    g_wh[p] = cvt2(src[(size_t)(2 * kp) * N + n], src[(size_t)(2 * kp + 1) * N + n]);
}

__global__ void k_split_x(const float* __restrict__ x) {
    int i = blockIdx.x * blockDim.x + threadIdx.x;
    if (i >= NN * HF / 4) return;
    float4 v = ((const float4*)x)[i];
    ((uint2*)g_aH)[i] = make_uint2(cvt2(v.x, v.y), cvt2(v.z, v.w));
}

// ---------------- bf16 MMA GEMM, cp.async double-buffered --------------------
// OMODE: 0 = fp32 out, 2 = bf162 out.

#define BM 128
#define SA 20
#define SBS 20

template <int BNT, int OMODE, bool FUSE>
__global__ void __launch_bounds__(256)
k_mma(const uint32_t* __restrict__ Ah, int wOff, const float* __restrict__ bias,
      float* __restrict__ Cf, uint32_t* __restrict__ OutH,
      int M, int K) {
    constexpr int NT = BNT / 16;
    constexpr int AW = BM * SA;
    constexpr int BW = BNT * SBS;
    constexpr int SW = AW + BW;

    extern __shared__ uint32_t smem[];

    const int tid = threadIdx.x;
    const int wid = tid >> 5;
    const int lane = tid & 31;
    const int wm = wid & 3;
    const int wn = wid >> 2;
    const int gid = lane >> 2;
    const int tig = lane & 3;
    const int bm = blockIdx.y * BM;
    const int Kp = K >> 1;
    const int KT = Kp >> 4;

    const uint32_t smB = (uint32_t)__cvta_generic_to_shared(smem);

    float c[2][NT][4];
#pragma unroll
    for (int mt = 0; mt < 2; mt++)
#pragma unroll
        for (int nt = 0; nt < NT; nt++)
#pragma unroll
            for (int j = 0; j < 4; j++) c[mt][nt][j] = 0.f;

    const int aRow = lane & 15;
    const int aKh = (lane >> 4) * 4;
    const int bN = (lane >> 4) * 8 + (lane & 7);
    const int bKh = ((lane >> 3) & 1) * 4;

    auto prefetch = [&](int kt, int buf) {
        const int k0p = kt * 16;
        uint32_t base = smB + (uint32_t)buf * SW * 4u;
#pragma unroll
        for (int i = 0; i < 2; i++) {
            int task = tid + i * 256;
            int row = task >> 2;
            int qg = (task & 3) * 4;
            int gr = bm + row;
            if (gr >= M) gr = M - 1;
            cpasync16(base + (uint32_t)(row * SA + qg) * 4u, &Ah[(size_t)gr * Kp + k0p + qg]);
        }
#pragma unroll
        for (int i = 0; i < BNT / 64; i++) {
            int task = tid + i * 256;
            int n = task >> 2;
            int qg = (task & 3) * 4;
            cpasync16(base + AW * 4u + (uint32_t)(n * SBS + qg) * 4u,
                      &g_wh[(size_t)wOff + (size_t)n * Kp + k0p + qg]);
        }
        cp_commit();
    };

    prefetch(0, 0);

    for (int kt = 0; kt < KT; kt++) {
        const int buf = kt & 1;
        if (kt + 1 < KT) {
            prefetch(kt + 1, buf ^ 1);
            cp_wait<1>();
        } else {
            cp_wait<0>();
        }
        __syncthreads();

        uint32_t sAhB = smB + (uint32_t)buf * SW * 4u;
        uint32_t sBhB = sAhB + AW * 4u;

#pragma unroll
        for (int ks = 0; ks < 2; ks++) {
            uint32_t ah[2][4];
#pragma unroll
            for (int mt = 0; mt < 2; mt++) {
                uint32_t woff = (uint32_t)((wm * 32 + mt * 16 + aRow) * SA + ks * 8 + aKh) * 4u;
                ldsm4(ah[mt], sAhB + woff);
            }
            uint32_t bh[NT][2];
#pragma unroll
            for (int j = 0; j < NT / 2; j++) {
                uint32_t woff = (uint32_t)((wn * (BNT / 2) + j * 16 + bN) * SBS + ks * 8 + bKh) * 4u;
                uint32_t rh[4];
                ldsm4(rh, sBhB + woff);
                bh[2 * j][0] = rh[0]; bh[2 * j][1] = rh[1];
                bh[2 * j + 1][0] = rh[2]; bh[2 * j + 1][1] = rh[3];
            }
#pragma unroll
            for (int mt = 0; mt < 2; mt++)
#pragma unroll
                for (int nt = 0; nt < NT; nt++)
                    mma16816(c[mt][nt], ah[mt], bh[nt]);
        }
        __syncthreads();
    }

    const int N = BNT;
#pragma unroll
    for (int mt = 0; mt < 2; mt++)
#pragma unroll
        for (int nt = 0; nt < NT; nt++) {
            int gr0 = bm + wm * 32 + mt * 16 + gid;
            int gc = wn * (BNT / 2) + nt * 8 + tig * 2;
            float v0 = c[mt][nt][0], v1 = c[mt][nt][1];
            float v2 = c[mt][nt][2], v3 = c[mt][nt][3];
            if (FUSE) {
                float b0 = bias[gc], b1 = bias[gc + 1];
                v0 = fmaxf(v0 + b0, 0.f);
                v1 = fmaxf(v1 + b1, 0.f);
                v2 = fmaxf(v2 + b0, 0.f);
                v3 = fmaxf(v3 + b1, 0.f);
            }
            if (OMODE == 2) {
                if (gr0 < M)
                    OutH[(size_t)gr0 * (N >> 1) + (gc >> 1)] = cvt2(v0, v1);
                if (gr0 + 8 < M)
                    OutH[(size_t)(gr0 + 8) * (N >> 1) + (gc >> 1)] = cvt2(v2, v3);
            } else {
                if (gr0 < M) *(float2*)&Cf[(size_t)gr0 * N + gc] = make_float2(v0, v1);
                if (gr0 + 8 < M) *(float2*)&Cf[(size_t)(gr0 + 8) * N + gc] = make_float2(v2, v3);
            }
        }
}

// ---------------- bf16 gather aggregation, bf16 output -----------------------
template <int F>
__global__ void k_agg(const uint32_t* __restrict__ h, const float* __restrict__ bias,
                      uint32_t* __restrict__ outH) {
    int warp = (blockIdx.x * blockDim.x + threadIdx.x) >> 5;
    int lane = threadIdx.x & 31;
    if (warp >= NN) return;
    const int FP = F / 2;
    const int VPL = F / 32;
    float di = g_dinv[warp];
    float di2 = di * di;
    float acc[VPL];

    auto loadrow = [&](int row, float2& a, float2& b) {
        if (VPL == 4) {
            uint2 v = *(const uint2*)(h + (size_t)row * FP + lane * 2);
            a = __bfloat1622float2(reinterpret_cast<__nv_bfloat162&>(v.x));
            b = __bfloat1622float2(reinterpret_cast<__nv_bfloat162&>(v.y));
        } else {
            uint32_t v = h[(size_t)row * FP + lane];
            a = __bfloat1622float2(reinterpret_cast<__nv_bfloat162&>(v));
        }
    };

    {
        float2 a, b;
        loadrow(warp, a, b);
        acc[0] = a.x * di2;
        acc[1] = a.y * di2;
        if (VPL == 4) { acc[2] = b.x * di2; acc[3] = b.y * di2; }
    }

    int beg = g_rowptr[warp];
    int end = g_rowptr[warp + 1];
    int j = beg;
    for (; j + 3 < end; j += 4) {
        int2 e0 = g_edge[j];
        int2 e1 = g_edge[j + 1];
        int2 e2 = g_edge[j + 2];
        int2 e3 = g_edge[j + 3];
        float w0 = __int_as_float(e0.y);
        float w1 = __int_as_float(e1.y);
        float w2 = __int_as_float(e2.y);
        float w3 = __int_as_float(e3.y);
        float2 a0, b0, a1, b1, a2, b2, a3, b3;
        loadrow(e0.x, a0, b0);
        loadrow(e1.x, a1, b1);
        loadrow(e2.x, a2, b2);
        loadrow(e3.x, a3, b3);
        acc[0] += a0.x * w0; acc[1] += a0.y * w0;
        acc[0] += a1.x * w1; acc[1] += a1.y * w1;
        acc[0] += a2.x * w2; acc[1] += a2.y * w2;
        acc[0] += a3.x * w3; acc[1] += a3.y * w3;
        if (VPL == 4) {
            acc[2] += b0.x * w0; acc[3] += b0.y * w0;
            acc[2] += b1.x * w1; acc[3] += b1.y * w1;
            acc[2] += b2.x * w2; acc[3] += b2.y * w2;
            acc[2] += b3.x * w3; acc[3] += b3.y * w3;
        }
    }
    for (; j < end; j++) {
        int2 e0 = g_edge[j];
        float w0 = __int_as_float(e0.y);
        float2 a0, b0;
        loadrow(e0.x, a0, b0);
        acc[0] += a0.x * w0; acc[1] += a0.y * w0;
        if (VPL == 4) { acc[2] += b0.x * w0; acc[3] += b0.y * w0; }
    }

    if (VPL == 4) {
        float4 b = *(const float4*)&bias[lane * 4];
        float o0 = fmaxf(acc[0] + b.x, 0.f);
        float o1 = fmaxf(acc[1] + b.y, 0.f);
        float o2 = fmaxf(acc[2] + b.z, 0.f);
        float o3 = fmaxf(acc[3] + b.w, 0.f);
        size_t p = (size_t)warp * FP + lane * 2;
        *(uint2*)&outH[p] = make_uint2(cvt2(o0, o1), cvt2(o2, o3));
    } else {
        float2 b = *(const float2*)&bias[lane * 2];
        float o0 = fmaxf(acc[0] + b.x, 0.f);
        float o1 = fmaxf(acc[1] + b.y, 0.f);
        outH[(size_t)warp * FP + lane] = cvt2(o0, o1);
    }
}

// ---------------- final 64->2 + log_softmax ----------------------------------
__global__ void k_final(const float* __restrict__ z, const float* __restrict__ Wc3,
                        const float* __restrict__ bc3, float* __restrict__ out) {
    __shared__ float sw[HF2 * 2];
    __shared__ float sb[2];
    if (threadIdx.x < HF2 * 2) sw[threadIdx.x] = Wc3[threadIdx.x];
    if (threadIdx.x < 2) sb[threadIdx.x] = bc3[threadIdx.x];
    __syncthreads();
    int g = blockIdx.x * blockDim.x + threadIdx.x;
    if (g >= BBG) return;
    const float* zr = z + (size_t)g * HF2;
    float a0 = sb[0], a1 = sb[1];
#pragma unroll
    for (int k = 0; k < HF2; k++) {
        float zv = zr[k];
        a0 += zv * sw[2 * k + 0];
        a1 += zv * sw[2 * k + 1];
    }
    float m = fmaxf(a0, a1);
    float l = logf(expf(a0 - m) + expf(a1 - m));
    out[2 * g + 0] = a0 - m - l;
    out[2 * g + 1] = a1 - m - l;
}

// ---------------- launch -----------------------------------------------------
extern "C" void kernel_launch(void* const* d_in, const int* in_sizes, int n_in,
                              void* d_out, int out_size) {
    const float* x   = (const float*)d_in[0];
    const int*   ei  = (const int*)d_in[1];
    const float* W1  = (const float*)d_in[2];
    const float* b1  = (const float*)d_in[3];
    const float* W2  = (const float*)d_in[4];
    const float* b2  = (const float*)d_in[5];
    const float* W3  = (const float*)d_in[6];
    const float* b3  = (const float*)d_in[7];
    const float* Wc1 = (const float*)d_in[8];
    const float* bc1 = (const float*)d_in[9];
    const float* Wc2 = (const float*)d_in[10];
    const float* bc2 = (const float*)d_in[11];
    const float* Wc3 = (const float*)d_in[12];
    const float* bc3 = (const float*)d_in[13];
    float* out = (float*)d_out;

    float* bufF;
    uint32_t* bufH;
    uint32_t* aH;
    cudaGetSymbolAddress((void**)&bufF, g_bufF);
    cudaGetSymbolAddress((void**)&bufH, g_bufH);
    cudaGetSymbolAddress((void**)&aH, g_aH);

    const int SM128 = 2 * (BM * SA + 128 * SBS) * 4;   // 40960
    const int SM64  = 2 * (BM * SA + 64 * SBS) * 4;    // 30720
    static bool attrDone = false;
    if (!attrDone) {
        cudaFuncSetAttribute(k_mma<128, 2, false>, cudaFuncAttributeMaxDynamicSharedMemorySize, SM128);
        cudaFuncSetAttribute(k_mma<64, 2, false>,  cudaFuncAttributeMaxDynamicSharedMemorySize, SM64);
        cudaFuncSetAttribute(k_mma<128, 2, true>,  cudaFuncAttributeMaxDynamicSharedMemorySize, SM128);
        cudaFuncSetAttribute(k_mma<64, 0, true>,   cudaFuncAttributeMaxDynamicSharedMemorySize, SM64);
        attrDone = true;
    }

    static cudaStream_t sB = nullptr;
    static cudaEvent_t evFork = nullptr, evJoin = nullptr;
    if (sB == nullptr) {
        cudaStreamCreateWithFlags(&sB, cudaStreamNonBlocking);
        cudaEventCreateWithFlags(&evFork, cudaEventDisableTiming);
        cudaEventCreateWithFlags(&evJoin, cudaEventDisableTiming);
    }

    const int aggBlocks = (NN * 32 + 255) / 256;
    dim3 gN(1, (NN + BM - 1) / BM);
    dim3 gC(1, (BBG + BM - 1) / BM);

    // --- fork: stream B does convert path + layer-1 GEMM ---
    cudaEventRecord(evFork, 0);
    cudaStreamWaitEvent(sB, evFork, 0);
    k_split_w<<<(WPAIRS + 255) / 256, 256, 0, sB>>>(W1, W2, W3, Wc1, Wc2);
    k_split_x<<<(NN * HF / 4 + 255) / 256, 256, 0, sB>>>(x);
    k_mma<128, 2, false><<<gN, 256, SM128, sB>>>(aH, WOFF1, nullptr, nullptr, bufH, NN, HF);
    cudaEventRecord(evJoin, sB);

    // --- default stream: CSR build ---
    k_zero_deg<<<(NN + 255) / 256, 256>>>();
    k_count<<<(EE + 255) / 256, 256>>>(ei);
    k_scan1<<<SCB, 1024>>>();
    k_scan2<<<1, 256>>>();
    k_scan3<<<SCB, 1024>>>();
    k_scatter<<<(EE + 255) / 256, 256>>>(ei);

    // --- join ---
    cudaStreamWaitEvent(0, evJoin, 0);

    // layer 1 agg
    k_agg<HF><<<aggBlocks, 256>>>(bufH, b1, aH);
    // layer 2
    k_mma<128, 2, false><<<gN, 256, SM128>>>(aH, WOFF2, nullptr, nullptr, bufH, NN, HF);
    k_agg<HF><<<aggBlocks, 256>>>(bufH, b2, aH);
    // layer 3 (128 -> 64)
    k_mma<64, 2, false><<<gN, 256, SM64>>>(aH, WOFF3, nullptr, nullptr, bufH, NN, HF);
    k_agg<HF2><<<aggBlocks, 256>>>(bufH, b3, aH);
    // classifier: input viewed as [50000, 192] (96 pairs/row)
    k_mma<128, 2, true><<<gC, 256, SM128>>>(aH, WOFFC1, bc1, nullptr, aH + COFF, BBG, 3 * HF2);
    k_mma<64, 0, true><<<gC, 256, SM64>>>(aH + COFF, WOFFC2, bc2, bufF, nullptr, BBG, HF);
    // final 64->2 + log_softmax
    k_final<<<(BBG + 255) / 256, 256>>>(bufF, Wc3, bc3, out);
}

// round 11
// speedup vs baseline: 2.4534x; 1.0993x over previous
#include <cuda_runtime.h>
#include <cuda_bf16.h>
#include <stdint.h>
#include <math.h>

#define NN 150000
#define EE 2400000
#define BBG 50000
#define HF 128
#define HF2 64

#define WOFF1  0
#define WOFF2  8192
#define WOFF3  16384
#define WOFFC1 20480
#define WOFFC2 32768
#define WPAIRS 36864

#define COFF   4800000   // classifier intermediate offset in aH (words)
#define SCB    147       // scan blocks: ceil(150000/1024)

// ---------------- scratch (static device globals; no allocation) -------------
__device__ uint32_t g_bufH[(size_t)NN * HF / 2];      // bf162 GEMM outputs (agg input)
__device__ uint32_t g_aH[(size_t)NN * HF / 2];        // bf162 activations (GEMM input)
__device__ uint32_t g_wh[WPAIRS];                     // bf162 weights, n-major [n][k/2]
__device__ float g_dinv[NN];
__device__ int2  g_edge[EE];                          // {src, dinv[src]-as-int}
__device__ int   g_deg[NN];
__device__ int   g_rowptr[NN + 1];
__device__ int   g_cursor[NN];
__device__ int   g_part[256];

// ---------------- helpers ----------------------------------------------------
__device__ __forceinline__ uint32_t cvt2(float x, float y) {
    __nv_bfloat162 h = __floats2bfloat162_rn(x, y);
    return reinterpret_cast<uint32_t&>(h);
}

__device__ __forceinline__ void mma16816(float c[4], const uint32_t a[4], const uint32_t b[2]) {
    asm volatile(
        "mma.sync.aligned.m16n8k16.row.col.f32.bf16.bf16.f32 "
        "{%0,%1,%2,%3}, {%4,%5,%6,%7}, {%8,%9}, {%0,%1,%2,%3};"
        : "+f"(c[0]), "+f"(c[1]), "+f"(c[2]), "+f"(c[3])
        : "r"(a[0]), "r"(a[1]), "r"(a[2]), "r"(a[3]), "r"(b[0]), "r"(b[1]));
}

__device__ __forceinline__ void ldsm4(uint32_t r[4], uint32_t saddr) {
    asm volatile(
        "ldmatrix.sync.aligned.m8n8.x4.shared.b16 {%0,%1,%2,%3}, [%4];"
        : "=r"(r[0]), "=r"(r[1]), "=r"(r[2]), "=r"(r[3]) : "r"(saddr));
}

__device__ __forceinline__ void cpasync16(uint32_t smem, const void* gptr) {
    asm volatile("cp.async.cg.shared.global [%0], [%1], 16;" :: "r"(smem), "l"(gptr));
}
__device__ __forceinline__ void cp_commit() {
    asm volatile("cp.async.commit_group;");
}
template <int Nw>
__device__ __forceinline__ void cp_wait() {
    asm volatile("cp.async.wait_group %0;" :: "n"(Nw));
}

// ---------------- setup kernels ---------------------------------------------
__global__ void k_count(const int* __restrict__ ei) {
    int e = blockIdx.x * blockDim.x + threadIdx.x;
    if (e < EE) atomicAdd(&g_deg[ei[EE + e]], 1);
}

__global__ void k_scan1() {
    __shared__ int s[1024];
    int t = threadIdx.x;
    int i = blockIdx.x * 1024 + t;
    s[t] = (i < NN) ? g_deg[i] : 0;
    __syncthreads();
    for (int off = 512; off; off >>= 1) {
        if (t < off) s[t] += s[t + off];
        __syncthreads();
    }
    if (t == 0) g_part[blockIdx.x] = s[0];
}

__global__ void k_scan2() {
    __shared__ int s[256];
    int t = threadIdx.x;
    int v = (t < SCB) ? g_part[t] : 0;
    s[t] = v;
    __syncthreads();
    for (int off = 1; off < 256; off <<= 1) {
        int u = (t >= off) ? s[t - off] : 0;
        __syncthreads();
        s[t] += u;
        __syncthreads();
    }
    if (t < SCB) g_part[t] = s[t] - v;
    if (t == 255) g_rowptr[NN] = s[255];
}

__global__ void k_scan3() {
    __shared__ int s[1024];
    int t = threadIdx.x;
    int i = blockIdx.x * 1024 + t;
    int d = (i < NN) ? g_deg[i] : 0;
    s[t] = d;
    __syncthreads();
    for (int off = 1; off < 1024; off <<= 1) {
        int u = (t >= off) ? s[t - off] : 0;
        __syncthreads();
        s[t] += u;
        __syncthreads();
    }
    if (i < NN) {
        int excl = s[t] - d + g_part[blockIdx.x];
        g_rowptr[i] = excl;
        g_cursor[i] = excl;
        g_dinv[i] = rsqrtf((float)(d + 1));
    }
}

// store (src, dinv[src]) — only ONE random load per edge
__global__ void k_scatter(const int* __restrict__ ei) {
    int e = blockIdx.x * blockDim.x + threadIdx.x;
    if (e < EE) {
        int srcn = ei[e];
        int dstn = ei[EE + e];
        int pos = atomicAdd(&g_cursor[dstn], 1);
        g_edge[pos] = make_int2(srcn, __float_as_int(g_dinv[srcn]));
    }
}

// convert weights once, n-major layout: wT[n][k/2] bf162 pairs
__global__ void k_split_w(const float* __restrict__ W1, const float* __restrict__ W2,
                          const float* __restrict__ W3, const float* __restrict__ Wc1,
                          const float* __restrict__ Wc2) {
    int p = blockIdx.x * blockDim.x + threadIdx.x;
    if (p >= WPAIRS) return;
    const float* src;
    int off, N, Kp;
    if (p < WOFF2)       { src = W1;  off = p - WOFF1;  N = 128; Kp = 64; }
    else if (p < WOFF3)  { src = W2;  off = p - WOFF2;  N = 128; Kp = 64; }
    else if (p < WOFFC1) { src = W3;  off = p - WOFF3;  N = 64;  Kp = 64; }
    else if (p < WOFFC2) { src = Wc1; off = p - WOFFC1; N = 128; Kp = 96; }
    else                 { src = Wc2; off = p - WOFFC2; N = 64;  Kp = 64; }
    int n = off / Kp, kp = off % Kp;
    g_wh[p] = cvt2(src[(size_t)(2 * kp) * N + n], src[(size_t)(2 * kp + 1) * N + n]);
}

__global__ void k_split_x(const float* __restrict__ x) {
    int i = blockIdx.x * blockDim.x + threadIdx.x;
    if (i >= NN * HF / 4) return;
    float4 v = ((const float4*)x)[i];
    ((uint2*)g_aH)[i] = make_uint2(cvt2(v.x, v.y), cvt2(v.z, v.w));
}

// ---------------- bf16 MMA GEMM, cp.async double-buffered --------------------
// OMODE: 2 = bf162 out, 3 = fused 64->2 + log_softmax (final classifier)

#define BM 128
#define SA 20
#define SBS 20

template <int BNT, int OMODE, bool FUSE>
__global__ void __launch_bounds__(256)
k_mma(const uint32_t* __restrict__ Ah, int wOff, const float* __restrict__ bias,
      float* __restrict__ Cf, uint32_t* __restrict__ OutH,
      int M, int K,
      const float* __restrict__ Wc3, const float* __restrict__ bc3) {
    constexpr int NT = BNT / 16;
    constexpr int AW = BM * SA;
    constexpr int BW = BNT * SBS;
    constexpr int SW = AW + BW;

    extern __shared__ uint32_t smem[];

    const int tid = threadIdx.x;
    const int wid = tid >> 5;
    const int lane = tid & 31;
    const int wm = wid & 3;
    const int wn = wid >> 2;
    const int gid = lane >> 2;
    const int tig = lane & 3;
    const int bm = blockIdx.y * BM;
    const int Kp = K >> 1;
    const int KT = Kp >> 4;

    const uint32_t smB = (uint32_t)__cvta_generic_to_shared(smem);

    float c[2][NT][4];
#pragma unroll
    for (int mt = 0; mt < 2; mt++)
#pragma unroll
        for (int nt = 0; nt < NT; nt++)
#pragma unroll
            for (int j = 0; j < 4; j++) c[mt][nt][j] = 0.f;

    const int aRow = lane & 15;
    const int aKh = (lane >> 4) * 4;
    const int bN = (lane >> 4) * 8 + (lane & 7);
    const int bKh = ((lane >> 3) & 1) * 4;

    auto prefetch = [&](int kt, int buf) {
        const int k0p = kt * 16;
        uint32_t base = smB + (uint32_t)buf * SW * 4u;
#pragma unroll
        for (int i = 0; i < 2; i++) {
            int task = tid + i * 256;
            int row = task >> 2;
            int qg = (task & 3) * 4;
            int gr = bm + row;
            if (gr >= M) gr = M - 1;
            cpasync16(base + (uint32_t)(row * SA + qg) * 4u, &Ah[(size_t)gr * Kp + k0p + qg]);
        }
#pragma unroll
        for (int i = 0; i < BNT / 64; i++) {
            int task = tid + i * 256;
            int n = task >> 2;
            int qg = (task & 3) * 4;
            cpasync16(base + AW * 4u + (uint32_t)(n * SBS + qg) * 4u,
                      &g_wh[(size_t)wOff + (size_t)n * Kp + k0p + qg]);
        }
        cp_commit();
    };

    prefetch(0, 0);

    for (int kt = 0; kt < KT; kt++) {
        const int buf = kt & 1;
        if (kt + 1 < KT) {
            prefetch(kt + 1, buf ^ 1);
            cp_wait<1>();
        } else {
            cp_wait<0>();
        }
        __syncthreads();

        uint32_t sAhB = smB + (uint32_t)buf * SW * 4u;
        uint32_t sBhB = sAhB + AW * 4u;

#pragma unroll
        for (int ks = 0; ks < 2; ks++) {
            uint32_t ah[2][4];
#pragma unroll
            for (int mt = 0; mt < 2; mt++) {
                uint32_t woff = (uint32_t)((wm * 32 + mt * 16 + aRow) * SA + ks * 8 + aKh) * 4u;
                ldsm4(ah[mt], sAhB + woff);
            }
            uint32_t bh[NT][2];
#pragma unroll
            for (int j = 0; j < NT / 2; j++) {
                uint32_t woff = (uint32_t)((wn * (BNT / 2) + j * 16 + bN) * SBS + ks * 8 + bKh) * 4u;
                uint32_t rh[4];
                ldsm4(rh, sBhB + woff);
                bh[2 * j][0] = rh[0]; bh[2 * j][1] = rh[1];
                bh[2 * j + 1][0] = rh[2]; bh[2 * j + 1][1] = rh[3];
            }
#pragma unroll
            for (int mt = 0; mt < 2; mt++)
#pragma unroll
                for (int nt = 0; nt < NT; nt++)
                    mma16816(c[mt][nt], ah[mt], bh[nt]);
        }
        __syncthreads();
    }

    const int N = BNT;
    float* smemF = (float*)smem;   // reused for OMODE==3 staging (post-loop, safe)
#pragma unroll
    for (int mt = 0; mt < 2; mt++)
#pragma unroll
        for (int nt = 0; nt < NT; nt++) {
            int r0 = wm * 32 + mt * 16 + gid;
            int gr0 = bm + r0;
            int gc = wn * (BNT / 2) + nt * 8 + tig * 2;
            float v0 = c[mt][nt][0], v1 = c[mt][nt][1];
            float v2 = c[mt][nt][2], v3 = c[mt][nt][3];
            if (FUSE) {
                float b0 = bias[gc], b1 = bias[gc + 1];
                v0 = fmaxf(v0 + b0, 0.f);
                v1 = fmaxf(v1 + b1, 0.f);
                v2 = fmaxf(v2 + b0, 0.f);
                v3 = fmaxf(v3 + b1, 0.f);
            }
            if (OMODE == 2) {
                if (gr0 < M)
                    OutH[(size_t)gr0 * (N >> 1) + (gc >> 1)] = cvt2(v0, v1);
                if (gr0 + 8 < M)
                    OutH[(size_t)(gr0 + 8) * (N >> 1) + (gc >> 1)] = cvt2(v2, v3);
            } else {  // OMODE == 3: stage to smem for fused final
                smemF[r0 * 65 + gc] = v0;
                smemF[r0 * 65 + gc + 1] = v1;
                smemF[(r0 + 8) * 65 + gc] = v2;
                smemF[(r0 + 8) * 65 + gc + 1] = v3;
            }
        }

    if (OMODE == 3) {
        __syncthreads();
        if (tid < BM) {
            int g = bm + tid;
            if (g < M) {
                float a0 = bc3[0], a1 = bc3[1];
                const float* zr = &smemF[tid * 65];
#pragma unroll
                for (int k = 0; k < HF2; k++) {
                    float zv = zr[k];
                    a0 += zv * Wc3[2 * k + 0];
                    a1 += zv * Wc3[2 * k + 1];
                }
                float m = fmaxf(a0, a1);
                float l = logf(expf(a0 - m) + expf(a1 - m));
                Cf[2 * g + 0] = a0 - m - l;
                Cf[2 * g + 1] = a1 - m - l;
            }
        }
    }
}

// ---------------- bf16 gather aggregation ------------------------------------
// out[i] = relu(b + di*(di*h[i] + sum_e dinv_src*h[src]));  edge.y = dinv_src
template <int F>
__global__ void k_agg(const uint32_t* __restrict__ h, const float* __restrict__ bias,
                      uint32_t* __restrict__ outH) {
    int warp = (blockIdx.x * blockDim.x + threadIdx.x) >> 5;
    int lane = threadIdx.x & 31;
    if (warp >= NN) return;
    const int FP = F / 2;
    const int VPL = F / 32;
    float di = g_dinv[warp];
    float acc[VPL];

    auto loadrow = [&](int row, float2& a, float2& b) {
        if (VPL == 4) {
            uint2 v = *(const uint2*)(h + (size_t)row * FP + lane * 2);
            a = __bfloat1622float2(reinterpret_cast<__nv_bfloat162&>(v.x));
            b = __bfloat1622float2(reinterpret_cast<__nv_bfloat162&>(v.y));
        } else {
            uint32_t v = h[(size_t)row * FP + lane];
            a = __bfloat1622float2(reinterpret_cast<__nv_bfloat162&>(v));
        }
    };

    {
        float2 a, b;
        loadrow(warp, a, b);
        acc[0] = a.x * di;
        acc[1] = a.y * di;
        if (VPL == 4) { acc[2] = b.x * di; acc[3] = b.y * di; }
    }

    int beg = g_rowptr[warp];
    int end = g_rowptr[warp + 1];
    int j = beg;
    for (; j + 3 < end; j += 4) {
        int2 e0 = g_edge[j];
        int2 e1 = g_edge[j + 1];
        int2 e2 = g_edge[j + 2];
        int2 e3 = g_edge[j + 3];
        float w0 = __int_as_float(e0.y);
        float w1 = __int_as_float(e1.y);
        float w2 = __int_as_float(e2.y);
        float w3 = __int_as_float(e3.y);
        float2 a0, b0, a1, b1, a2, b2, a3, b3;
        loadrow(e0.x, a0, b0);
        loadrow(e1.x, a1, b1);
        loadrow(e2.x, a2, b2);
        loadrow(e3.x, a3, b3);
        acc[0] += a0.x * w0; acc[1] += a0.y * w0;
        acc[0] += a1.x * w1; acc[1] += a1.y * w1;
        acc[0] += a2.x * w2; acc[1] += a2.y * w2;
        acc[0] += a3.x * w3; acc[1] += a3.y * w3;
        if (VPL == 4) {
            acc[2] += b0.x * w0; acc[3] += b0.y * w0;
            acc[2] += b1.x * w1; acc[3] += b1.y * w1;
            acc[2] += b2.x * w2; acc[3] += b2.y * w2;
            acc[2] += b3.x * w3; acc[3] += b3.y * w3;
        }
    }
    for (; j < end; j++) {
        int2 e0 = g_edge[j];
        float w0 = __int_as_float(e0.y);
        float2 a0, b0;
        loadrow(e0.x, a0, b0);
        acc[0] += a0.x * w0; acc[1] += a0.y * w0;
        if (VPL == 4) { acc[2] += b0.x * w0; acc[3] += b0.y * w0; }
    }

    if (VPL == 4) {
        float4 b = *(const float4*)&bias[lane * 4];
        float o0 = fmaxf(acc[0] * di + b.x, 0.f);
        float o1 = fmaxf(acc[1] * di + b.y, 0.f);
        float o2 = fmaxf(acc[2] * di + b.z, 0.f);
        float o3 = fmaxf(acc[3] * di + b.w, 0.f);
        size_t p = (size_t)warp * FP + lane * 2;
        *(uint2*)&outH[p] = make_uint2(cvt2(o0, o1), cvt2(o2, o3));
    } else {
        float2 b = *(const float2*)&bias[lane * 2];
        float o0 = fmaxf(acc[0] * di + b.x, 0.f);
        float o1 = fmaxf(acc[1] * di + b.y, 0.f);
        outH[(size_t)warp * FP + lane] = cvt2(o0, o1);
    }
}

// ---------------- launch -----------------------------------------------------
extern "C" void kernel_launch(void* const* d_in, const int* in_sizes, int n_in,
                              void* d_out, int out_size) {
    const float* x   = (const float*)d_in[0];
    const int*   ei  = (const int*)d_in[1];
    const float* W1  = (const float*)d_in[2];
    const float* b1  = (const float*)d_in[3];
    const float* W2  = (const float*)d_in[4];
    const float* b2  = (const float*)d_in[5];
    const float* W3  = (const float*)d_in[6];
    const float* b3  = (const float*)d_in[7];
    const float* Wc1 = (const float*)d_in[8];
    const float* bc1 = (const float*)d_in[9];
    const float* Wc2 = (const float*)d_in[10];
    const float* bc2 = (const float*)d_in[11];
    const float* Wc3 = (const float*)d_in[12];
    const float* bc3 = (const float*)d_in[13];
    float* out = (float*)d_out;

    uint32_t* bufH;
    uint32_t* aH;
    void* degPtr;
    cudaGetSymbolAddress((void**)&bufH, g_bufH);
    cudaGetSymbolAddress((void**)&aH, g_aH);
    cudaGetSymbolAddress(&degPtr, g_deg);

    const int SM128 = 2 * (BM * SA + 128 * SBS) * 4;   // 40960
    const int SM64  = 2 * (BM * SA + 64 * SBS) * 4;    // 30720
    const int SMF   = BM * 65 * 4;                     // 33280 (fused final staging)
    static bool attrDone = false;
    if (!attrDone) {
        cudaFuncSetAttribute(k_mma<128, 2, false>, cudaFuncAttributeMaxDynamicSharedMemorySize, SM128);
        cudaFuncSetAttribute(k_mma<64, 2, false>,  cudaFuncAttributeMaxDynamicSharedMemorySize, SM64);
        cudaFuncSetAttribute(k_mma<128, 2, true>,  cudaFuncAttributeMaxDynamicSharedMemorySize, SM128);
        cudaFuncSetAttribute(k_mma<64, 3, true>,   cudaFuncAttributeMaxDynamicSharedMemorySize, SMF);
        attrDone = true;
    }

    static cudaStream_t sB = nullptr;
    static cudaEvent_t evFork = nullptr, evJoin = nullptr;
    if (sB == nullptr) {
        cudaStreamCreateWithFlags(&sB, cudaStreamNonBlocking);
        cudaEventCreateWithFlags(&evFork, cudaEventDisableTiming);
        cudaEventCreateWithFlags(&evJoin, cudaEventDisableTiming);
    }

    const int aggBlocks = (NN * 32 + 255) / 256;
    dim3 gN(1, (NN + BM - 1) / BM);
    dim3 gC(1, (BBG + BM - 1) / BM);

    // --- fork: stream B does convert path + layer-1 GEMM ---
    cudaEventRecord(evFork, 0);
    cudaStreamWaitEvent(sB, evFork, 0);
    k_split_w<<<(WPAIRS + 255) / 256, 256, 0, sB>>>(W1, W2, W3, Wc1, Wc2);
    k_split_x<<<(NN * HF / 4 + 255) / 256, 256, 0, sB>>>(x);
    k_mma<128, 2, false><<<gN, 256, SM128, sB>>>(aH, WOFF1, nullptr, nullptr, bufH, NN, HF, nullptr, nullptr);
    cudaEventRecord(evJoin, sB);

    // --- default stream: CSR build ---
    cudaMemsetAsync(degPtr, 0, NN * sizeof(int), 0);
    k_count<<<(EE + 255) / 256, 256>>>(ei);
    k_scan1<<<SCB, 1024>>>();
    k_scan2<<<1, 256>>>();
    k_scan3<<<SCB, 1024>>>();
    k_scatter<<<(EE + 255) / 256, 256>>>(ei);

    // --- join ---
    cudaStreamWaitEvent(0, evJoin, 0);

    // layer 1 agg
    k_agg<HF><<<aggBlocks, 256>>>(bufH, b1, aH);
    // layer 2
    k_mma<128, 2, false><<<gN, 256, SM128>>>(aH, WOFF2, nullptr, nullptr, bufH, NN, HF, nullptr, nullptr);
    k_agg<HF><<<aggBlocks, 256>>>(bufH, b2, aH);
    // layer 3 (128 -> 64)
    k_mma<64, 2, false><<<gN, 256, SM64>>>(aH, WOFF3, nullptr, nullptr, bufH, NN, HF, nullptr, nullptr);
    k_agg<HF2><<<aggBlocks, 256>>>(bufH, b3, aH);
    // classifier: input viewed as [50000, 192] (96 pairs/row)
    k_mma<128, 2, true><<<gC, 256, SM128>>>(aH, WOFFC1, bc1, nullptr, aH + COFF, BBG, 3 * HF2, nullptr, nullptr);
    // gc2 + fused 64->2 + log_softmax
    k_mma<64, 3, true><<<gC, 256, SMF>>>(aH + COFF, WOFFC2, bc2, out, nullptr, BBG, HF, Wc3, bc3);
}